// round 11
// baseline (speedup 1.0000x reference)
#include <cuda_runtime.h>
#include <cuda_bf16.h>
#include <math.h>
#include <stdint.h>

// Problem constants
#define BB   2
#define NN   2048
#define EE   1024
#define HH   16
#define MLPD 4096
#define MR   (BB * NN)   // 4096 token rows

// ---------------- scratch (static device globals; no allocation) ----------------
__device__ __nv_bfloat16 g_h[MR * EE];               // LN output (bf16)
__device__ __nv_bfloat16 g_qkv[MR * 3 * EE];         // QKV (bf16)
__device__ __nv_bfloat16 g_attn[MR * EE];            // attention out (bf16)
__device__ float         g_x1[MR * EE];              // residual 1 (fp32)
__device__ __nv_bfloat16 g_mlp[(size_t)MR * MLPD];   // GELU(fc1) (bf16)
__device__ __nv_bfloat16 g_wqkvT[3 * EE * EE];       // transposed weights [N,K] bf16
__device__ __nv_bfloat16 g_wprojT[EE * EE];
__device__ __nv_bfloat16 g_wfc1T[(size_t)MLPD * EE];
__device__ __nv_bfloat16 g_wfc2T[(size_t)EE * MLPD];

// ======================= helpers =================================
__device__ __forceinline__ uint32_t smem_u32(const void* p) {
    uint32_t a;
    asm("{ .reg .u64 t; cvta.to.shared.u64 t, %1; cvt.u32.u64 %0, t; }" : "=r"(a) : "l"(p));
    return a;
}
__device__ __forceinline__ float ex2(float x) {
    float r;
    asm("ex2.approx.ftz.f32 %0, %1;" : "=f"(r) : "f"(x));
    return r;
}
__device__ __forceinline__ uint32_t pack_bf16(float lo, float hi) {
    uint32_t r;
    asm("cvt.rn.bf16x2.f32 %0, %1, %2;" : "=r"(r) : "f"(hi), "f"(lo));
    return r;
}
__device__ __forceinline__ uint32_t scale_bf16x2(uint32_t v, float s) {
    const __nv_bfloat162 b = *reinterpret_cast<const __nv_bfloat162*>(&v);
    return pack_bf16(__bfloat162float(b.x) * s, __bfloat162float(b.y) * s);
}
__device__ __forceinline__ void cp16(uint32_t dst, const void* src) {
    asm volatile("cp.async.cg.shared.global [%0], [%1], 16;" :: "r"(dst), "l"(src));
}
#define CP_COMMIT() asm volatile("cp.async.commit_group;" ::: "memory")
#define CP_WAIT1()  asm volatile("cp.async.wait_group 1;" ::: "memory")

__device__ __forceinline__ void mma_bf16(float* c, const uint32_t* a, const uint32_t* b) {
    asm volatile(
        "mma.sync.aligned.m16n8k16.row.col.f32.bf16.bf16.f32 "
        "{%0,%1,%2,%3}, {%4,%5,%6,%7}, {%8,%9}, {%0,%1,%2,%3};"
        : "+f"(c[0]), "+f"(c[1]), "+f"(c[2]), "+f"(c[3])
        : "r"(a[0]), "r"(a[1]), "r"(a[2]), "r"(a[3]), "r"(b[0]), "r"(b[1]));
}
__device__ __forceinline__ void ldsm_x4(uint32_t* r, uint32_t addr) {
    asm volatile("ldmatrix.sync.aligned.m8n8.x4.shared.b16 {%0,%1,%2,%3}, [%4];"
                 : "=r"(r[0]), "=r"(r[1]), "=r"(r[2]), "=r"(r[3]) : "r"(addr));
}
__device__ __forceinline__ void ldsm_x4t(uint32_t* r, uint32_t addr) {
    asm volatile("ldmatrix.sync.aligned.m8n8.x4.trans.shared.b16 {%0,%1,%2,%3}, [%4];"
                 : "=r"(r[0]), "=r"(r[1]), "=r"(r[2]), "=r"(r[3]) : "r"(addr));
}

// ---------------- fused transpose of all 4 weights: one launch -------------------
#define T_QKV  3072
#define T_PROJ (T_QKV + 1024)
#define T_FC1  (T_PROJ + 4096)
#define T_FC2  (T_FC1 + 4096)

__global__ void transpose_all(const float* __restrict__ w0, const float* __restrict__ w1,
                              const float* __restrict__ w2, const float* __restrict__ w3,
                              __nv_bfloat16* __restrict__ o0, __nv_bfloat16* __restrict__ o1,
                              __nv_bfloat16* __restrict__ o2, __nv_bfloat16* __restrict__ o3) {
    __shared__ float t[32][33];
    int tt = blockIdx.x;
    const float* in;
    __nv_bfloat16* out;
    int R, C;
    if (tt < T_QKV)       { in = w0; out = o0; R = EE;   C = 3 * EE; }
    else if (tt < T_PROJ) { in = w1; out = o1; R = EE;   C = EE;   tt -= T_QKV;  }
    else if (tt < T_FC1)  { in = w2; out = o2; R = EE;   C = MLPD; tt -= T_PROJ; }
    else                  { in = w3; out = o3; R = MLPD; C = EE;   tt -= T_FC1;  }
    const int ctiles = C >> 5;
    const int bx = tt % ctiles, by = tt / ctiles;

    const int c = bx * 32 + threadIdx.x;
    const int r0 = by * 32;
    #pragma unroll
    for (int i = threadIdx.y; i < 32; i += 8)
        t[i][threadIdx.x] = in[(size_t)(r0 + i) * C + c];
    __syncthreads();
    const int rc = by * 32 + threadIdx.x;
    const int c0 = bx * 32;
    #pragma unroll
    for (int i = threadIdx.y; i < 32; i += 8)
        out[(size_t)(c0 + i) * R + rc] = __float2bfloat16_rn(t[threadIdx.x][i]);
}

// ---------------- LayerNorm fp32 -> bf16 -----------------------------------------
__global__ void ln_kernel(const float* __restrict__ x, const float* __restrict__ g,
                          const float* __restrict__ beta,
                          __nv_bfloat16* __restrict__ out) {
    __shared__ float sh[8];
    const int row = blockIdx.x;
    const int tid = threadIdx.x;
    const float4 v = ((const float4*)(x + (size_t)row * EE))[tid];

    float s = v.x + v.y + v.z + v.w;
    #pragma unroll
    for (int o = 16; o; o >>= 1) s += __shfl_down_sync(0xffffffffu, s, o);
    if ((tid & 31) == 0) sh[tid >> 5] = s;
    __syncthreads();
    if (tid < 32) {
        float t = (tid < 8) ? sh[tid] : 0.f;
        #pragma unroll
        for (int o = 4; o; o >>= 1) t += __shfl_down_sync(0xffffffffu, t, o);
        if (tid == 0) sh[0] = t;
    }
    __syncthreads();
    const float mu = sh[0] * (1.0f / EE);
    __syncthreads();

    float dx = v.x - mu, dy = v.y - mu, dz = v.z - mu, dw = v.w - mu;
    float q = dx * dx + dy * dy + dz * dz + dw * dw;
    #pragma unroll
    for (int o = 16; o; o >>= 1) q += __shfl_down_sync(0xffffffffu, q, o);
    if ((tid & 31) == 0) sh[tid >> 5] = q;
    __syncthreads();
    if (tid < 32) {
        float t = (tid < 8) ? sh[tid] : 0.f;
        #pragma unroll
        for (int o = 4; o; o >>= 1) t += __shfl_down_sync(0xffffffffu, t, o);
        if (tid == 0) sh[0] = t;
    }
    __syncthreads();
    const float rstd = rsqrtf(sh[0] * (1.0f / EE) + 1e-5f);

    const float4 gv = ((const float4*)g)[tid];
    const float4 bv = ((const float4*)beta)[tid];
    uint2 o;
    o.x = pack_bf16(dx * rstd * gv.x + bv.x, dy * rstd * gv.y + bv.y);
    o.y = pack_bf16(dz * rstd * gv.z + bv.z, dw * rstd * gv.w + bv.w);
    ((uint2*)(out + (size_t)row * EE))[tid] = o;
}

// ---------------- bf16 mma.sync GEMM: CTA 128x256, 512 threads, 16 warps ---------
// warp tile 64x32 (2m x 8n warp grid); 3-stage ring, one barrier per K-chunk.
#define ASTR 72
#define STG  ((128 + 256) * ASTR)
#define GEMM_SMEM_BYTES (3 * STG * 2)

__device__ __forceinline__ void issue_tile(const __nv_bfloat16* __restrict__ A,
                                           const __nv_bfloat16* __restrict__ BT,
                                           __nv_bfloat16* stage, int bm, int bn,
                                           int kc, int K, int tid) {
    __nv_bfloat16* sA = stage;
    __nv_bfloat16* sB = stage + 128 * ASTR;
    #pragma unroll
    for (int p = 0; p < 2; p++) {
        const int e = p * 512 + tid;
        const int row = e >> 3, ch = e & 7;
        cp16(smem_u32(sA + row * ASTR + ch * 8),
             A + (size_t)(bm + row) * K + kc * 64 + ch * 8);
    }
    #pragma unroll
    for (int p = 0; p < 4; p++) {
        const int e = p * 512 + tid;
        const int row = e >> 3, ch = e & 7;
        cp16(smem_u32(sB + row * ASTR + ch * 8),
             BT + (size_t)(bn + row) * K + kc * 64 + ch * 8);
    }
}

template <int EPI>
__global__ __launch_bounds__(512, 1)
void gemm_mma(const __nv_bfloat16* __restrict__ A, const __nv_bfloat16* __restrict__ BT,
              const float* __restrict__ bias, const float* __restrict__ res,
              void* __restrict__ Cout, int M, int N, int K) {
    extern __shared__ __align__(16) __nv_bfloat16 smem[];
    const int tid  = threadIdx.x;
    const int lane = tid & 31, warp = tid >> 5;
    const int wm = warp >> 3, wn = warp & 7;     // 2m x 8n warps, 64x32 warp tiles
    const int gq = lane >> 2, tq = lane & 3;
    const int l15 = lane & 15;
    const int arow = l15, asel = lane >> 4;
    const int g  = lane >> 3, r8 = lane & 7;
    const int brow_off = (g >> 1) * 8 + r8;
    const int bcol_off = (g & 1) * 8;
    const int bm = blockIdx.y << 7;
    const int bn = blockIdx.x << 8;
    const int NC = K >> 6;

    float c[4][4][4];
    #pragma unroll
    for (int i = 0; i < 4; i++)
        #pragma unroll
        for (int j = 0; j < 4; j++)
            #pragma unroll
            for (int k = 0; k < 4; k++) c[i][j][k] = 0.f;

    issue_tile(A, BT, smem,       bm, bn, 0, K, tid); CP_COMMIT();
    issue_tile(A, BT, smem + STG, bm, bn, 1, K, tid); CP_COMMIT();

    int st = 0;
    for (int kc = 0; kc < NC; kc++) {
        CP_WAIT1();
        __syncthreads();
        if (kc + 2 < NC) {
            int nst = st + 2; if (nst >= 3) nst -= 3;
            issue_tile(A, BT, smem + nst * STG, bm, bn, kc + 2, K, tid);
        }
        CP_COMMIT();
        const __nv_bfloat16* sa = smem + st * STG + (size_t)(wm * 64) * ASTR;
        const __nv_bfloat16* sb = smem + st * STG + (size_t)128 * ASTR + (size_t)(wn * 32) * ASTR;
        #pragma unroll
        for (int ks = 0; ks < 4; ks++) {
            uint32_t af[4][4], bf[2][4];
            #pragma unroll
            for (int mt = 0; mt < 4; mt++)
                ldsm_x4(af[mt], smem_u32(sa + (mt * 16 + arow) * ASTR + ks * 16 + asel * 8));
            #pragma unroll
            for (int np = 0; np < 2; np++)
                ldsm_x4(bf[np], smem_u32(sb + (np * 16 + brow_off) * ASTR + ks * 16 + bcol_off));
            #pragma unroll
            for (int mt = 0; mt < 4; mt++)
                #pragma unroll
                for (int np = 0; np < 2; np++) {
                    mma_bf16(c[mt][2 * np + 0], af[mt], bf[np] + 0);
                    mma_bf16(c[mt][2 * np + 1], af[mt], bf[np] + 2);
                }
        }
        if (++st >= 3) st = 0;
    }

    // ---- epilogue ----
    #pragma unroll
    for (int nt = 0; nt < 4; nt++) {
        const int col = bn + wn * 32 + nt * 8 + 2 * tq;
        const float bx = bias[col], by = bias[col + 1];
        #pragma unroll
        for (int mt = 0; mt < 4; mt++) {
            const int row0 = bm + wm * 64 + mt * 16 + gq;
            #pragma unroll
            for (int half = 0; half < 2; half++) {
                const int row = row0 + half * 8;
                float vx = c[mt][nt][half * 2 + 0] + bx;
                float vy = c[mt][nt][half * 2 + 1] + by;
                if (EPI == 1) {
                    vx = 0.5f * vx * (1.0f + erff(vx * 0.70710678118654752f));
                    vy = 0.5f * vy * (1.0f + erff(vy * 0.70710678118654752f));
                }
                if (EPI == 2) {
                    const float2 rv = *(const float2*)(res + (size_t)row * N + col);
                    float2 o; o.x = vx + rv.x; o.y = vy + rv.y;
                    *(float2*)((float*)Cout + (size_t)row * N + col) = o;
                } else {
                    *(uint32_t*)((__nv_bfloat16*)Cout + (size_t)row * N + col) =
                        pack_bf16(vx, vy);
                }
            }
        }
    }
}

// ---------------- Flash attention: 256 queries/CTA, 32 rows/warp (R10) -----------
#define KVS 72
#define NT  (NN / 64)

__global__ __launch_bounds__(256, 1)
void attn_mma(const __nv_bfloat16* __restrict__ qkv, __nv_bfloat16* __restrict__ out) {
    __shared__ __nv_bfloat16 Kb[3][64 * KVS];
    __shared__ __nv_bfloat16 Vb[3][64 * KVS];
    const int tid  = threadIdx.x;
    const int lane = tid & 31, warp = tid >> 5;
    const int gq = lane >> 2, tq = lane & 3;
    const int g  = lane >> 3, r8 = lane & 7;
    const int krow_off = (g >> 1) * 8 + r8;
    const int kcol_off = (g & 1) * 8;
    const int vrow_off = (g & 1) * 8 + r8;
    const int vcol_off = (g >> 1) * 8;
    const int bh = blockIdx.y;
    const int b = bh >> 4, h = bh & 15;
    const int q0 = blockIdx.x * 256;

    uint32_t kbase[3], vbase[3];
    #pragma unroll
    for (int s = 0; s < 3; s++) {
        kbase[s] = smem_u32(&Kb[s][krow_off * KVS + kcol_off]);
        vbase[s] = smem_u32(&Vb[s][vrow_off * KVS + vcol_off]);
    }

    const float qsc = 0.125f * 1.4426950408889634f;
    uint32_t aq[2][4][4];
    #pragma unroll
    for (int mi = 0; mi < 2; mi++) {
        const __nv_bfloat16* r0 =
            qkv + (size_t)(b * NN + q0 + warp * 32 + mi * 16 + gq) * 3072 + h * 64;
        const __nv_bfloat16* r1 = r0 + (size_t)8 * 3072;
        #pragma unroll
        for (int ks = 0; ks < 4; ks++) {
            aq[mi][ks][0] = scale_bf16x2(*(const uint32_t*)(r0 + ks * 16 + 2 * tq), qsc);
            aq[mi][ks][1] = scale_bf16x2(*(const uint32_t*)(r1 + ks * 16 + 2 * tq), qsc);
            aq[mi][ks][2] = scale_bf16x2(*(const uint32_t*)(r0 + ks * 16 + 2 * tq + 8), qsc);
            aq[mi][ks][3] = scale_bf16x2(*(const uint32_t*)(r1 + ks * 16 + 2 * tq + 8), qsc);
        }
    }

    float oc[2][8][4];
    #pragma unroll
    for (int mi = 0; mi < 2; mi++)
        #pragma unroll
        for (int i = 0; i < 8; i++)
            #pragma unroll
            for (int j = 0; j < 4; j++) oc[mi][i][j] = 0.f;
    float mrow[2][2] = { {-1e30f, -1e30f}, {-1e30f, -1e30f} };
    float lrow[2][2] = { {0.f, 0.f}, {0.f, 0.f} };

    auto issue_kv = [&](int buf, int kt) {
        #pragma unroll
        for (int it = 0; it < 2; it++) {
            const int e = it * 256 + tid;
            const int row = e >> 3, ch = e & 7;
            const size_t gbase = (size_t)(b * NN + kt * 64 + row) * 3072 + h * 64 + ch * 8;
            cp16(smem_u32(&Kb[buf][row * KVS + ch * 8]), qkv + gbase + 1024);
            cp16(smem_u32(&Vb[buf][row * KVS + ch * 8]), qkv + gbase + 2048);
        }
    };

    issue_kv(0, 0); CP_COMMIT();
    issue_kv(1, 1); CP_COMMIT();

    int st = 0;
    for (int kt = 0; kt < NT; kt++) {
        CP_WAIT1();
        __syncthreads();
        if (kt + 2 < NT) {
            int nst = st + 2; if (nst >= 3) nst -= 3;
            issue_kv(nst, kt + 2);
        }
        CP_COMMIT();
        const uint32_t ka = kbase[st];
        const uint32_t va = vbase[st];

        float sc[2][8][4];
        #pragma unroll
        for (int mi = 0; mi < 2; mi++)
            #pragma unroll
            for (int i = 0; i < 8; i++)
                #pragma unroll
                for (int j = 0; j < 4; j++) sc[mi][i][j] = 0.f;
        #pragma unroll
        for (int ks = 0; ks < 4; ks++) {
            #pragma unroll
            for (int np = 0; np < 4; np++) {
                uint32_t b4[4];
                ldsm_x4(b4, ka + (uint32_t)((np * 16 * KVS + ks * 16) * 2));
                #pragma unroll
                for (int mi = 0; mi < 2; mi++) {
                    mma_bf16(sc[mi][2 * np + 0], aq[mi][ks], b4 + 0);
                    mma_bf16(sc[mi][2 * np + 1], aq[mi][ks], b4 + 2);
                }
            }
        }

        float f[2][2];
        #pragma unroll
        for (int mi = 0; mi < 2; mi++) {
            float mx0 = -1e30f, mx1 = -1e30f;
            #pragma unroll
            for (int nt = 0; nt < 8; nt++) {
                mx0 = fmaxf(mx0, fmaxf(sc[mi][nt][0], sc[mi][nt][1]));
                mx1 = fmaxf(mx1, fmaxf(sc[mi][nt][2], sc[mi][nt][3]));
            }
            mx0 = fmaxf(mx0, __shfl_xor_sync(0xffffffffu, mx0, 1));
            mx0 = fmaxf(mx0, __shfl_xor_sync(0xffffffffu, mx0, 2));
            mx1 = fmaxf(mx1, __shfl_xor_sync(0xffffffffu, mx1, 1));
            mx1 = fmaxf(mx1, __shfl_xor_sync(0xffffffffu, mx1, 2));
            const float mn0 = fmaxf(mrow[mi][0], mx0);
            const float mn1 = fmaxf(mrow[mi][1], mx1);
            f[mi][0] = ex2(mrow[mi][0] - mn0);
            f[mi][1] = ex2(mrow[mi][1] - mn1);
            mrow[mi][0] = mn0; mrow[mi][1] = mn1;
            lrow[mi][0] *= f[mi][0]; lrow[mi][1] *= f[mi][1];
            #pragma unroll
            for (int dt = 0; dt < 8; dt++) {
                oc[mi][dt][0] *= f[mi][0]; oc[mi][dt][1] *= f[mi][0];
                oc[mi][dt][2] *= f[mi][1]; oc[mi][dt][3] *= f[mi][1];
            }
        }

        #pragma unroll
        for (int j = 0; j < 4; j++) {
            uint32_t pa[2][4];
            #pragma unroll
            for (int mi = 0; mi < 2; mi++) {
                const int t0 = 2 * j, t1 = 2 * j + 1;
                const float m0 = mrow[mi][0], m1 = mrow[mi][1];
                const float p00 = ex2(sc[mi][t0][0] - m0), p01 = ex2(sc[mi][t0][1] - m0);
                const float p02 = ex2(sc[mi][t0][2] - m1), p03 = ex2(sc[mi][t0][3] - m1);
                const float p10 = ex2(sc[mi][t1][0] - m0), p11 = ex2(sc[mi][t1][1] - m0);
                const float p12 = ex2(sc[mi][t1][2] - m1), p13 = ex2(sc[mi][t1][3] - m1);
                lrow[mi][0] += p00 + p01 + p10 + p11;
                lrow[mi][1] += p02 + p03 + p12 + p13;
                pa[mi][0] = pack_bf16(p00, p01); pa[mi][1] = pack_bf16(p02, p03);
                pa[mi][2] = pack_bf16(p10, p11); pa[mi][3] = pack_bf16(p12, p13);
            }
            #pragma unroll
            for (int dp = 0; dp < 4; dp++) {
                uint32_t b4[4];
                ldsm_x4t(b4, va + (uint32_t)((16 * j * KVS + dp * 16) * 2));
                #pragma unroll
                for (int mi = 0; mi < 2; mi++) {
                    mma_bf16(oc[mi][2 * dp + 0], pa[mi], b4 + 0);
                    mma_bf16(oc[mi][2 * dp + 1], pa[mi], b4 + 2);
                }
            }
        }
        if (++st >= 3) st = 0;
    }

    #pragma unroll
    for (int mi = 0; mi < 2; mi++) {
        float l0 = lrow[mi][0], l1 = lrow[mi][1];
        l0 += __shfl_xor_sync(0xffffffffu, l0, 1);
        l0 += __shfl_xor_sync(0xffffffffu, l0, 2);
        l1 += __shfl_xor_sync(0xffffffffu, l1, 1);
        l1 += __shfl_xor_sync(0xffffffffu, l1, 2);
        const float inv0 = 1.f / l0, inv1 = 1.f / l1;
        const int row0 = b * NN + q0 + warp * 32 + mi * 16 + gq;
        __nv_bfloat16* o0 = out + (size_t)row0 * EE + h * 64;
        __nv_bfloat16* o1 = o0 + (size_t)8 * EE;
        #pragma unroll
        for (int dt = 0; dt < 8; dt++) {
            *(uint32_t*)(o0 + dt * 8 + 2 * tq) =
                pack_bf16(oc[mi][dt][0] * inv0, oc[mi][dt][1] * inv0);
            *(uint32_t*)(o1 + dt * 8 + 2 * tq) =
                pack_bf16(oc[mi][dt][2] * inv1, oc[mi][dt][3] * inv1);
        }
    }
}

// ---------------- host launch ---------------------------------------------------
extern "C" void kernel_launch(void* const* d_in, const int* in_sizes, int n_in,
                              void* d_out, int out_size) {
    const float* x      = (const float*)d_in[0];
    const float* w_qkv  = (const float*)d_in[1];
    const float* b_qkv  = (const float*)d_in[2];
    const float* w_proj = (const float*)d_in[3];
    const float* b_proj = (const float*)d_in[4];
    const float* g1     = (const float*)d_in[5];
    const float* beta1  = (const float*)d_in[6];
    const float* g2     = (const float*)d_in[7];
    const float* beta2  = (const float*)d_in[8];
    const float* w_fc1  = (const float*)d_in[9];
    const float* b_fc1  = (const float*)d_in[10];
    const float* w_fc2  = (const float*)d_in[11];
    const float* b_fc2  = (const float*)d_in[12];
    float* out = (float*)d_out;

    __nv_bfloat16 *h, *qkv, *attn, *mlp, *wqkvT, *wprojT, *wfc1T, *wfc2T;
    float* x1;
    cudaGetSymbolAddress((void**)&h,      g_h);
    cudaGetSymbolAddress((void**)&qkv,    g_qkv);
    cudaGetSymbolAddress((void**)&attn,   g_attn);
    cudaGetSymbolAddress((void**)&x1,     g_x1);
    cudaGetSymbolAddress((void**)&mlp,    g_mlp);
    cudaGetSymbolAddress((void**)&wqkvT,  g_wqkvT);
    cudaGetSymbolAddress((void**)&wprojT, g_wprojT);
    cudaGetSymbolAddress((void**)&wfc1T,  g_wfc1T);
    cudaGetSymbolAddress((void**)&wfc2T,  g_wfc2T);

    cudaFuncSetAttribute(gemm_mma<0>, cudaFuncAttributeMaxDynamicSharedMemorySize, GEMM_SMEM_BYTES);
    cudaFuncSetAttribute(gemm_mma<1>, cudaFuncAttributeMaxDynamicSharedMemorySize, GEMM_SMEM_BYTES);
    cudaFuncSetAttribute(gemm_mma<2>, cudaFuncAttributeMaxDynamicSharedMemorySize, GEMM_SMEM_BYTES);

    transpose_all<<<T_FC2, dim3(32, 8)>>>(w_qkv, w_proj, w_fc1, w_fc2,
                                          wqkvT, wprojT, wfc1T, wfc2T);

    // 1. h = LN(x) -> bf16
    ln_kernel<<<MR, 256>>>(x, g1, beta1, h);
    // 2. qkv = h @ w_qkv + b_qkv -> bf16
    gemm_mma<0><<<dim3(3 * EE / 256, MR / 128), 512, GEMM_SMEM_BYTES>>>(
        h, wqkvT, b_qkv, nullptr, qkv, MR, 3 * EE, EE);
    // 3. attention -> bf16 (256 queries per CTA)
    attn_mma<<<dim3(NN / 256, BB * HH), 256>>>(qkv, attn);
    // 4. x1 = attn @ w_proj + b_proj + x -> fp32
    gemm_mma<2><<<dim3(EE / 256, MR / 128), 512, GEMM_SMEM_BYTES>>>(
        attn, wprojT, b_proj, x, x1, MR, EE, EE);
    // 5. h = LN(x1) -> bf16
    ln_kernel<<<MR, 256>>>(x1, g2, beta2, h);
    // 6. mlp = gelu(h @ w_fc1 + b_fc1) -> bf16
    gemm_mma<1><<<dim3(MLPD / 256, MR / 128), 512, GEMM_SMEM_BYTES>>>(
        h, wfc1T, b_fc1, nullptr, mlp, MR, MLPD, EE);
    // 7. out = mlp @ w_fc2 + b_fc2 + x1 -> fp32
    gemm_mma<2><<<dim3(EE / 256, MR / 128), 512, GEMM_SMEM_BYTES>>>(
        mlp, wfc2T, b_fc2, x1, out, MR, EE, MLPD);
}

// round 12
// speedup vs baseline: 1.0456x; 1.0456x over previous
#include <cuda_runtime.h>
#include <cuda_bf16.h>
#include <math.h>
#include <stdint.h>

// Problem constants
#define BB   2
#define NN   2048
#define EE   1024
#define HH   16
#define MLPD 4096
#define MR   (BB * NN)   // 4096 token rows

// ---------------- scratch (static device globals; no allocation) ----------------
__device__ __nv_bfloat16 g_h[MR * EE];               // LN output (bf16)
__device__ __nv_bfloat16 g_qkv[MR * 3 * EE];         // QKV (bf16)
__device__ __nv_bfloat16 g_attn[MR * EE];            // attention out (bf16)
__device__ float         g_x1[MR * EE];              // residual 1 (fp32)
__device__ __nv_bfloat16 g_mlp[(size_t)MR * MLPD];   // GELU(fc1) (bf16)
__device__ __nv_bfloat16 g_wqkvT[3 * EE * EE];       // transposed weights [N,K] bf16
__device__ __nv_bfloat16 g_wprojT[EE * EE];
__device__ __nv_bfloat16 g_wfc1T[(size_t)MLPD * EE];
__device__ __nv_bfloat16 g_wfc2T[(size_t)EE * MLPD];

// ======================= helpers =================================
__device__ __forceinline__ uint32_t smem_u32(const void* p) {
    uint32_t a;
    asm("{ .reg .u64 t; cvta.to.shared.u64 t, %1; cvt.u32.u64 %0, t; }" : "=r"(a) : "l"(p));
    return a;
}
__device__ __forceinline__ float ex2(float x) {
    float r;
    asm("ex2.approx.ftz.f32 %0, %1;" : "=f"(r) : "f"(x));
    return r;
}
__device__ __forceinline__ uint32_t pack_bf16(float lo, float hi) {
    uint32_t r;
    asm("cvt.rn.bf16x2.f32 %0, %1, %2;" : "=r"(r) : "f"(hi), "f"(lo));
    return r;
}
__device__ __forceinline__ uint32_t scale_bf16x2(uint32_t v, float s) {
    const __nv_bfloat162 b = *reinterpret_cast<const __nv_bfloat162*>(&v);
    return pack_bf16(__bfloat162float(b.x) * s, __bfloat162float(b.y) * s);
}
__device__ __forceinline__ void cp16(uint32_t dst, const void* src) {
    asm volatile("cp.async.cg.shared.global [%0], [%1], 16;" :: "r"(dst), "l"(src));
}
#define CP_COMMIT() asm volatile("cp.async.commit_group;" ::: "memory")
#define CP_WAIT1()  asm volatile("cp.async.wait_group 1;" ::: "memory")

__device__ __forceinline__ void mma_bf16(float* c, const uint32_t* a, const uint32_t* b) {
    asm volatile(
        "mma.sync.aligned.m16n8k16.row.col.f32.bf16.bf16.f32 "
        "{%0,%1,%2,%3}, {%4,%5,%6,%7}, {%8,%9}, {%0,%1,%2,%3};"
        : "+f"(c[0]), "+f"(c[1]), "+f"(c[2]), "+f"(c[3])
        : "r"(a[0]), "r"(a[1]), "r"(a[2]), "r"(a[3]), "r"(b[0]), "r"(b[1]));
}
__device__ __forceinline__ void ldsm_x4(uint32_t* r, uint32_t addr) {
    asm volatile("ldmatrix.sync.aligned.m8n8.x4.shared.b16 {%0,%1,%2,%3}, [%4];"
                 : "=r"(r[0]), "=r"(r[1]), "=r"(r[2]), "=r"(r[3]) : "r"(addr));
}
__device__ __forceinline__ void ldsm_x4t(uint32_t* r, uint32_t addr) {
    asm volatile("ldmatrix.sync.aligned.m8n8.x4.trans.shared.b16 {%0,%1,%2,%3}, [%4];"
                 : "=r"(r[0]), "=r"(r[1]), "=r"(r[2]), "=r"(r[3]) : "r"(addr));
}

// ---------------- fused transpose of all 4 weights: one launch -------------------
#define T_QKV  3072
#define T_PROJ (T_QKV + 1024)
#define T_FC1  (T_PROJ + 4096)
#define T_FC2  (T_FC1 + 4096)

__global__ void transpose_all(const float* __restrict__ w0, const float* __restrict__ w1,
                              const float* __restrict__ w2, const float* __restrict__ w3,
                              __nv_bfloat16* __restrict__ o0, __nv_bfloat16* __restrict__ o1,
                              __nv_bfloat16* __restrict__ o2, __nv_bfloat16* __restrict__ o3) {
    __shared__ float t[32][33];
    int tt = blockIdx.x;
    const float* in;
    __nv_bfloat16* out;
    int R, C;
    if (tt < T_QKV)       { in = w0; out = o0; R = EE;   C = 3 * EE; }
    else if (tt < T_PROJ) { in = w1; out = o1; R = EE;   C = EE;   tt -= T_QKV;  }
    else if (tt < T_FC1)  { in = w2; out = o2; R = EE;   C = MLPD; tt -= T_PROJ; }
    else                  { in = w3; out = o3; R = MLPD; C = EE;   tt -= T_FC1;  }
    const int ctiles = C >> 5;
    const int bx = tt % ctiles, by = tt / ctiles;

    const int c = bx * 32 + threadIdx.x;
    const int r0 = by * 32;
    #pragma unroll
    for (int i = threadIdx.y; i < 32; i += 8)
        t[i][threadIdx.x] = in[(size_t)(r0 + i) * C + c];
    __syncthreads();
    const int rc = by * 32 + threadIdx.x;
    const int c0 = bx * 32;
    #pragma unroll
    for (int i = threadIdx.y; i < 32; i += 8)
        out[(size_t)(c0 + i) * R + rc] = __float2bfloat16_rn(t[threadIdx.x][i]);
}

// ---------------- LayerNorm fp32 -> bf16 -----------------------------------------
__global__ void ln_kernel(const float* __restrict__ x, const float* __restrict__ g,
                          const float* __restrict__ beta,
                          __nv_bfloat16* __restrict__ out) {
    __shared__ float sh[8];
    const int row = blockIdx.x;
    const int tid = threadIdx.x;
    const float4 v = ((const float4*)(x + (size_t)row * EE))[tid];

    float s = v.x + v.y + v.z + v.w;
    #pragma unroll
    for (int o = 16; o; o >>= 1) s += __shfl_down_sync(0xffffffffu, s, o);
    if ((tid & 31) == 0) sh[tid >> 5] = s;
    __syncthreads();
    if (tid < 32) {
        float t = (tid < 8) ? sh[tid] : 0.f;
        #pragma unroll
        for (int o = 4; o; o >>= 1) t += __shfl_down_sync(0xffffffffu, t, o);
        if (tid == 0) sh[0] = t;
    }
    __syncthreads();
    const float mu = sh[0] * (1.0f / EE);
    __syncthreads();

    float dx = v.x - mu, dy = v.y - mu, dz = v.z - mu, dw = v.w - mu;
    float q = dx * dx + dy * dy + dz * dz + dw * dw;
    #pragma unroll
    for (int o = 16; o; o >>= 1) q += __shfl_down_sync(0xffffffffu, q, o);
    if ((tid & 31) == 0) sh[tid >> 5] = q;
    __syncthreads();
    if (tid < 32) {
        float t = (tid < 8) ? sh[tid] : 0.f;
        #pragma unroll
        for (int o = 4; o; o >>= 1) t += __shfl_down_sync(0xffffffffu, t, o);
        if (tid == 0) sh[0] = t;
    }
    __syncthreads();
    const float rstd = rsqrtf(sh[0] * (1.0f / EE) + 1e-5f);

    const float4 gv = ((const float4*)g)[tid];
    const float4 bv = ((const float4*)beta)[tid];
    uint2 o;
    o.x = pack_bf16(dx * rstd * gv.x + bv.x, dy * rstd * gv.y + bv.y);
    o.y = pack_bf16(dz * rstd * gv.z + bv.z, dw * rstd * gv.w + bv.w);
    ((uint2*)(out + (size_t)row * EE))[tid] = o;
}

// ---------------- bf16 mma.sync GEMM: CTA 128x128, 256 threads, occupancy 2 ------
// 8 warps (2m x 4n), warp tile 64x32; 3-stage ring, one barrier per K-chunk.
#define ASTR 72
#define STG  ((128 + 128) * ASTR)
#define GEMM_SMEM_BYTES (3 * STG * 2)   // 110592 bytes -> 2 CTAs/SM

__device__ __forceinline__ void issue_tile(const __nv_bfloat16* __restrict__ A,
                                           const __nv_bfloat16* __restrict__ BT,
                                           __nv_bfloat16* stage, int bm, int bn,
                                           int kc, int K, int tid) {
    __nv_bfloat16* sA = stage;
    __nv_bfloat16* sB = stage + 128 * ASTR;
    #pragma unroll
    for (int p = 0; p < 4; p++) {
        const int e = p * 256 + tid;
        const int row = e >> 3, ch = e & 7;
        cp16(smem_u32(sA + row * ASTR + ch * 8),
             A + (size_t)(bm + row) * K + kc * 64 + ch * 8);
        cp16(smem_u32(sB + row * ASTR + ch * 8),
             BT + (size_t)(bn + row) * K + kc * 64 + ch * 8);
    }
}

template <int EPI>
__global__ __launch_bounds__(256, 2)
void gemm_mma(const __nv_bfloat16* __restrict__ A, const __nv_bfloat16* __restrict__ BT,
              const float* __restrict__ bias, const float* __restrict__ res,
              void* __restrict__ Cout, int M, int N, int K) {
    extern __shared__ __align__(16) __nv_bfloat16 smem[];
    const int tid  = threadIdx.x;
    const int lane = tid & 31, warp = tid >> 5;
    const int wm = warp >> 2, wn = warp & 3;     // 2m x 4n warps, 64x32 warp tiles
    const int gq = lane >> 2, tq = lane & 3;
    const int l15 = lane & 15;
    const int arow = l15, asel = lane >> 4;
    const int g  = lane >> 3, r8 = lane & 7;
    const int brow_off = (g >> 1) * 8 + r8;
    const int bcol_off = (g & 1) * 8;
    const int bm = blockIdx.y << 7;
    const int bn = blockIdx.x << 7;
    const int NC = K >> 6;

    float c[4][4][4];
    #pragma unroll
    for (int i = 0; i < 4; i++)
        #pragma unroll
        for (int j = 0; j < 4; j++)
            #pragma unroll
            for (int k = 0; k < 4; k++) c[i][j][k] = 0.f;

    issue_tile(A, BT, smem,       bm, bn, 0, K, tid); CP_COMMIT();
    issue_tile(A, BT, smem + STG, bm, bn, 1, K, tid); CP_COMMIT();

    int st = 0;
    for (int kc = 0; kc < NC; kc++) {
        CP_WAIT1();
        __syncthreads();
        if (kc + 2 < NC) {
            int nst = st + 2; if (nst >= 3) nst -= 3;
            issue_tile(A, BT, smem + nst * STG, bm, bn, kc + 2, K, tid);
        }
        CP_COMMIT();
        const __nv_bfloat16* sa = smem + st * STG + (size_t)(wm * 64) * ASTR;
        const __nv_bfloat16* sb = smem + st * STG + (size_t)128 * ASTR + (size_t)(wn * 32) * ASTR;
        #pragma unroll
        for (int ks = 0; ks < 4; ks++) {
            uint32_t af[4][4], bf[2][4];
            #pragma unroll
            for (int mt = 0; mt < 4; mt++)
                ldsm_x4(af[mt], smem_u32(sa + (mt * 16 + arow) * ASTR + ks * 16 + asel * 8));
            #pragma unroll
            for (int np = 0; np < 2; np++)
                ldsm_x4(bf[np], smem_u32(sb + (np * 16 + brow_off) * ASTR + ks * 16 + bcol_off));
            #pragma unroll
            for (int mt = 0; mt < 4; mt++)
                #pragma unroll
                for (int np = 0; np < 2; np++) {
                    mma_bf16(c[mt][2 * np + 0], af[mt], bf[np] + 0);
                    mma_bf16(c[mt][2 * np + 1], af[mt], bf[np] + 2);
                }
        }
        if (++st >= 3) st = 0;
    }

    // ---- epilogue ----
    #pragma unroll
    for (int nt = 0; nt < 4; nt++) {
        const int col = bn + wn * 32 + nt * 8 + 2 * tq;
        const float bx = bias[col], by = bias[col + 1];
        #pragma unroll
        for (int mt = 0; mt < 4; mt++) {
            const int row0 = bm + wm * 64 + mt * 16 + gq;
            #pragma unroll
            for (int half = 0; half < 2; half++) {
                const int row = row0 + half * 8;
                float vx = c[mt][nt][half * 2 + 0] + bx;
                float vy = c[mt][nt][half * 2 + 1] + by;
                if (EPI == 1) {
                    vx = 0.5f * vx * (1.0f + erff(vx * 0.70710678118654752f));
                    vy = 0.5f * vy * (1.0f + erff(vy * 0.70710678118654752f));
                }
                if (EPI == 2) {
                    const float2 rv = *(const float2*)(res + (size_t)row * N + col);
                    float2 o; o.x = vx + rv.x; o.y = vy + rv.y;
                    *(float2*)((float*)Cout + (size_t)row * N + col) = o;
                } else {
                    *(uint32_t*)((__nv_bfloat16*)Cout + (size_t)row * N + col) =
                        pack_bf16(vx, vy);
                }
            }
        }
    }
}

// ---------------- Flash attention: 256 queries/CTA, 32 rows/warp (R10) -----------
#define KVS 72
#define NT  (NN / 64)

__global__ __launch_bounds__(256, 1)
void attn_mma(const __nv_bfloat16* __restrict__ qkv, __nv_bfloat16* __restrict__ out) {
    __shared__ __nv_bfloat16 Kb[3][64 * KVS];
    __shared__ __nv_bfloat16 Vb[3][64 * KVS];
    const int tid  = threadIdx.x;
    const int lane = tid & 31, warp = tid >> 5;
    const int gq = lane >> 2, tq = lane & 3;
    const int g  = lane >> 3, r8 = lane & 7;
    const int krow_off = (g >> 1) * 8 + r8;
    const int kcol_off = (g & 1) * 8;
    const int vrow_off = (g & 1) * 8 + r8;
    const int vcol_off = (g >> 1) * 8;
    const int bh = blockIdx.y;
    const int b = bh >> 4, h = bh & 15;
    const int q0 = blockIdx.x * 256;

    uint32_t kbase[3], vbase[3];
    #pragma unroll
    for (int s = 0; s < 3; s++) {
        kbase[s] = smem_u32(&Kb[s][krow_off * KVS + kcol_off]);
        vbase[s] = smem_u32(&Vb[s][vrow_off * KVS + vcol_off]);
    }

    const float qsc = 0.125f * 1.4426950408889634f;
    uint32_t aq[2][4][4];
    #pragma unroll
    for (int mi = 0; mi < 2; mi++) {
        const __nv_bfloat16* r0 =
            qkv + (size_t)(b * NN + q0 + warp * 32 + mi * 16 + gq) * 3072 + h * 64;
        const __nv_bfloat16* r1 = r0 + (size_t)8 * 3072;
        #pragma unroll
        for (int ks = 0; ks < 4; ks++) {
            aq[mi][ks][0] = scale_bf16x2(*(const uint32_t*)(r0 + ks * 16 + 2 * tq), qsc);
            aq[mi][ks][1] = scale_bf16x2(*(const uint32_t*)(r1 + ks * 16 + 2 * tq), qsc);
            aq[mi][ks][2] = scale_bf16x2(*(const uint32_t*)(r0 + ks * 16 + 2 * tq + 8), qsc);
            aq[mi][ks][3] = scale_bf16x2(*(const uint32_t*)(r1 + ks * 16 + 2 * tq + 8), qsc);
        }
    }

    float oc[2][8][4];
    #pragma unroll
    for (int mi = 0; mi < 2; mi++)
        #pragma unroll
        for (int i = 0; i < 8; i++)
            #pragma unroll
            for (int j = 0; j < 4; j++) oc[mi][i][j] = 0.f;
    float mrow[2][2] = { {-1e30f, -1e30f}, {-1e30f, -1e30f} };
    float lrow[2][2] = { {0.f, 0.f}, {0.f, 0.f} };

    auto issue_kv = [&](int buf, int kt) {
        #pragma unroll
        for (int it = 0; it < 2; it++) {
            const int e = it * 256 + tid;
            const int row = e >> 3, ch = e & 7;
            const size_t gbase = (size_t)(b * NN + kt * 64 + row) * 3072 + h * 64 + ch * 8;
            cp16(smem_u32(&Kb[buf][row * KVS + ch * 8]), qkv + gbase + 1024);
            cp16(smem_u32(&Vb[buf][row * KVS + ch * 8]), qkv + gbase + 2048);
        }
    };

    issue_kv(0, 0); CP_COMMIT();
    issue_kv(1, 1); CP_COMMIT();

    int st = 0;
    for (int kt = 0; kt < NT; kt++) {
        CP_WAIT1();
        __syncthreads();
        if (kt + 2 < NT) {
            int nst = st + 2; if (nst >= 3) nst -= 3;
            issue_kv(nst, kt + 2);
        }
        CP_COMMIT();
        const uint32_t ka = kbase[st];
        const uint32_t va = vbase[st];

        float sc[2][8][4];
        #pragma unroll
        for (int mi = 0; mi < 2; mi++)
            #pragma unroll
            for (int i = 0; i < 8; i++)
                #pragma unroll
                for (int j = 0; j < 4; j++) sc[mi][i][j] = 0.f;
        #pragma unroll
        for (int ks = 0; ks < 4; ks++) {
            #pragma unroll
            for (int np = 0; np < 4; np++) {
                uint32_t b4[4];
                ldsm_x4(b4, ka + (uint32_t)((np * 16 * KVS + ks * 16) * 2));
                #pragma unroll
                for (int mi = 0; mi < 2; mi++) {
                    mma_bf16(sc[mi][2 * np + 0], aq[mi][ks], b4 + 0);
                    mma_bf16(sc[mi][2 * np + 1], aq[mi][ks], b4 + 2);
                }
            }
        }

        float f[2][2];
        #pragma unroll
        for (int mi = 0; mi < 2; mi++) {
            float mx0 = -1e30f, mx1 = -1e30f;
            #pragma unroll
            for (int nt = 0; nt < 8; nt++) {
                mx0 = fmaxf(mx0, fmaxf(sc[mi][nt][0], sc[mi][nt][1]));
                mx1 = fmaxf(mx1, fmaxf(sc[mi][nt][2], sc[mi][nt][3]));
            }
            mx0 = fmaxf(mx0, __shfl_xor_sync(0xffffffffu, mx0, 1));
            mx0 = fmaxf(mx0, __shfl_xor_sync(0xffffffffu, mx0, 2));
            mx1 = fmaxf(mx1, __shfl_xor_sync(0xffffffffu, mx1, 1));
            mx1 = fmaxf(mx1, __shfl_xor_sync(0xffffffffu, mx1, 2));
            const float mn0 = fmaxf(mrow[mi][0], mx0);
            const float mn1 = fmaxf(mrow[mi][1], mx1);
            f[mi][0] = ex2(mrow[mi][0] - mn0);
            f[mi][1] = ex2(mrow[mi][1] - mn1);
            mrow[mi][0] = mn0; mrow[mi][1] = mn1;
            lrow[mi][0] *= f[mi][0]; lrow[mi][1] *= f[mi][1];
            #pragma unroll
            for (int dt = 0; dt < 8; dt++) {
                oc[mi][dt][0] *= f[mi][0]; oc[mi][dt][1] *= f[mi][0];
                oc[mi][dt][2] *= f[mi][1]; oc[mi][dt][3] *= f[mi][1];
            }
        }

        #pragma unroll
        for (int j = 0; j < 4; j++) {
            uint32_t pa[2][4];
            #pragma unroll
            for (int mi = 0; mi < 2; mi++) {
                const int t0 = 2 * j, t1 = 2 * j + 1;
                const float m0 = mrow[mi][0], m1 = mrow[mi][1];
                const float p00 = ex2(sc[mi][t0][0] - m0), p01 = ex2(sc[mi][t0][1] - m0);
                const float p02 = ex2(sc[mi][t0][2] - m1), p03 = ex2(sc[mi][t0][3] - m1);
                const float p10 = ex2(sc[mi][t1][0] - m0), p11 = ex2(sc[mi][t1][1] - m0);
                const float p12 = ex2(sc[mi][t1][2] - m1), p13 = ex2(sc[mi][t1][3] - m1);
                lrow[mi][0] += p00 + p01 + p10 + p11;
                lrow[mi][1] += p02 + p03 + p12 + p13;
                pa[mi][0] = pack_bf16(p00, p01); pa[mi][1] = pack_bf16(p02, p03);
                pa[mi][2] = pack_bf16(p10, p11); pa[mi][3] = pack_bf16(p12, p13);
            }
            #pragma unroll
            for (int dp = 0; dp < 4; dp++) {
                uint32_t b4[4];
                ldsm_x4t(b4, va + (uint32_t)((16 * j * KVS + dp * 16) * 2));
                #pragma unroll
                for (int mi = 0; mi < 2; mi++) {
                    mma_bf16(oc[mi][2 * dp + 0], pa[mi], b4 + 0);
                    mma_bf16(oc[mi][2 * dp + 1], pa[mi], b4 + 2);
                }
            }
        }
        if (++st >= 3) st = 0;
    }

    #pragma unroll
    for (int mi = 0; mi < 2; mi++) {
        float l0 = lrow[mi][0], l1 = lrow[mi][1];
        l0 += __shfl_xor_sync(0xffffffffu, l0, 1);
        l0 += __shfl_xor_sync(0xffffffffu, l0, 2);
        l1 += __shfl_xor_sync(0xffffffffu, l1, 1);
        l1 += __shfl_xor_sync(0xffffffffu, l1, 2);
        const float inv0 = 1.f / l0, inv1 = 1.f / l1;
        const int row0 = b * NN + q0 + warp * 32 + mi * 16 + gq;
        __nv_bfloat16* o0 = out + (size_t)row0 * EE + h * 64;
        __nv_bfloat16* o1 = o0 + (size_t)8 * EE;
        #pragma unroll
        for (int dt = 0; dt < 8; dt++) {
            *(uint32_t*)(o0 + dt * 8 + 2 * tq) =
                pack_bf16(oc[mi][dt][0] * inv0, oc[mi][dt][1] * inv0);
            *(uint32_t*)(o1 + dt * 8 + 2 * tq) =
                pack_bf16(oc[mi][dt][2] * inv1, oc[mi][dt][3] * inv1);
        }
    }
}

// ---------------- host launch ---------------------------------------------------
extern "C" void kernel_launch(void* const* d_in, const int* in_sizes, int n_in,
                              void* d_out, int out_size) {
    const float* x      = (const float*)d_in[0];
    const float* w_qkv  = (const float*)d_in[1];
    const float* b_qkv  = (const float*)d_in[2];
    const float* w_proj = (const float*)d_in[3];
    const float* b_proj = (const float*)d_in[4];
    const float* g1     = (const float*)d_in[5];
    const float* beta1  = (const float*)d_in[6];
    const float* g2     = (const float*)d_in[7];
    const float* beta2  = (const float*)d_in[8];
    const float* w_fc1  = (const float*)d_in[9];
    const float* b_fc1  = (const float*)d_in[10];
    const float* w_fc2  = (const float*)d_in[11];
    const float* b_fc2  = (const float*)d_in[12];
    float* out = (float*)d_out;

    __nv_bfloat16 *h, *qkv, *attn, *mlp, *wqkvT, *wprojT, *wfc1T, *wfc2T;
    float* x1;
    cudaGetSymbolAddress((void**)&h,      g_h);
    cudaGetSymbolAddress((void**)&qkv,    g_qkv);
    cudaGetSymbolAddress((void**)&attn,   g_attn);
    cudaGetSymbolAddress((void**)&x1,     g_x1);
    cudaGetSymbolAddress((void**)&mlp,    g_mlp);
    cudaGetSymbolAddress((void**)&wqkvT,  g_wqkvT);
    cudaGetSymbolAddress((void**)&wprojT, g_wprojT);
    cudaGetSymbolAddress((void**)&wfc1T,  g_wfc1T);
    cudaGetSymbolAddress((void**)&wfc2T,  g_wfc2T);

    cudaFuncSetAttribute(gemm_mma<0>, cudaFuncAttributeMaxDynamicSharedMemorySize, GEMM_SMEM_BYTES);
    cudaFuncSetAttribute(gemm_mma<1>, cudaFuncAttributeMaxDynamicSharedMemorySize, GEMM_SMEM_BYTES);
    cudaFuncSetAttribute(gemm_mma<2>, cudaFuncAttributeMaxDynamicSharedMemorySize, GEMM_SMEM_BYTES);

    transpose_all<<<T_FC2, dim3(32, 8)>>>(w_qkv, w_proj, w_fc1, w_fc2,
                                          wqkvT, wprojT, wfc1T, wfc2T);

    // 1. h = LN(x) -> bf16
    ln_kernel<<<MR, 256>>>(x, g1, beta1, h);
    // 2. qkv = h @ w_qkv + b_qkv -> bf16
    gemm_mma<0><<<dim3(3 * EE / 128, MR / 128), 256, GEMM_SMEM_BYTES>>>(
        h, wqkvT, b_qkv, nullptr, qkv, MR, 3 * EE, EE);
    // 3. attention -> bf16 (256 queries per CTA)
    attn_mma<<<dim3(NN / 256, BB * HH), 256>>>(qkv, attn);
    // 4. x1 = attn @ w_proj + b_proj + x -> fp32
    gemm_mma<2><<<dim3(EE / 128, MR / 128), 256, GEMM_SMEM_BYTES>>>(
        attn, wprojT, b_proj, x, x1, MR, EE, EE);
    // 5. h = LN(x1) -> bf16
    ln_kernel<<<MR, 256>>>(x1, g2, beta2, h);
    // 6. mlp = gelu(h @ w_fc1 + b_fc1) -> bf16
    gemm_mma<1><<<dim3(MLPD / 128, MR / 128), 256, GEMM_SMEM_BYTES>>>(
        h, wfc1T, b_fc1, nullptr, mlp, MR, MLPD, EE);
    // 7. out = mlp @ w_fc2 + b_fc2 + x1 -> fp32
    gemm_mma<2><<<dim3(EE / 128, MR / 128), 256, GEMM_SMEM_BYTES>>>(
        mlp, wfc2T, b_fc2, x1, out, MR, EE, MLPD);
}

// round 13
// speedup vs baseline: 1.1254x; 1.0763x over previous
#include <cuda_runtime.h>
#include <cuda_bf16.h>
#include <math.h>
#include <stdint.h>

// Problem constants
#define BB   2
#define NN   2048
#define EE   1024
#define HH   16
#define MLPD 4096
#define MR   (BB * NN)   // 4096 token rows

// ---------------- scratch (static device globals; no allocation) ----------------
__device__ __nv_bfloat16 g_h[MR * EE];               // LN output (bf16)
__device__ __nv_bfloat16 g_qkv[MR * 3 * EE];         // QKV (bf16)
__device__ __nv_bfloat16 g_attn[MR * EE];            // attention out (bf16)
__device__ float         g_x1[MR * EE];              // residual 1 (fp32)
__device__ __nv_bfloat16 g_mlp[(size_t)MR * MLPD];   // GELU(fc1) (bf16)
__device__ __nv_bfloat16 g_wqkvT[3 * EE * EE];       // transposed weights [N,K] bf16
__device__ __nv_bfloat16 g_wprojT[EE * EE];
__device__ __nv_bfloat16 g_wfc1T[(size_t)MLPD * EE];
__device__ __nv_bfloat16 g_wfc2T[(size_t)EE * MLPD];

// ======================= helpers =================================
__device__ __forceinline__ uint32_t smem_u32(const void* p) {
    uint32_t a;
    asm("{ .reg .u64 t; cvta.to.shared.u64 t, %1; cvt.u32.u64 %0, t; }" : "=r"(a) : "l"(p));
    return a;
}
__device__ __forceinline__ float ex2(float x) {
    float r;
    asm("ex2.approx.ftz.f32 %0, %1;" : "=f"(r) : "f"(x));
    return r;
}
__device__ __forceinline__ uint32_t pack_bf16(float lo, float hi) {
    uint32_t r;
    asm("cvt.rn.bf16x2.f32 %0, %1, %2;" : "=r"(r) : "f"(hi), "f"(lo));
    return r;
}
__device__ __forceinline__ uint32_t scale_bf16x2(uint32_t v, float s) {
    const __nv_bfloat162 b = *reinterpret_cast<const __nv_bfloat162*>(&v);
    return pack_bf16(__bfloat162float(b.x) * s, __bfloat162float(b.y) * s);
}
__device__ __forceinline__ void cp16(uint32_t dst, const void* src) {
    asm volatile("cp.async.cg.shared.global [%0], [%1], 16;" :: "r"(dst), "l"(src));
}
#define CP_COMMIT() asm volatile("cp.async.commit_group;" ::: "memory")
#define CP_WAIT1()  asm volatile("cp.async.wait_group 1;" ::: "memory")

__device__ __forceinline__ void mma_bf16(float* c, const uint32_t* a, const uint32_t* b) {
    asm volatile(
        "mma.sync.aligned.m16n8k16.row.col.f32.bf16.bf16.f32 "
        "{%0,%1,%2,%3}, {%4,%5,%6,%7}, {%8,%9}, {%0,%1,%2,%3};"
        : "+f"(c[0]), "+f"(c[1]), "+f"(c[2]), "+f"(c[3])
        : "r"(a[0]), "r"(a[1]), "r"(a[2]), "r"(a[3]), "r"(b[0]), "r"(b[1]));
}
__device__ __forceinline__ void ldsm_x4(uint32_t* r, uint32_t addr) {
    asm volatile("ldmatrix.sync.aligned.m8n8.x4.shared.b16 {%0,%1,%2,%3}, [%4];"
                 : "=r"(r[0]), "=r"(r[1]), "=r"(r[2]), "=r"(r[3]) : "r"(addr));
}
__device__ __forceinline__ void ldsm_x4t(uint32_t* r, uint32_t addr) {
    asm volatile("ldmatrix.sync.aligned.m8n8.x4.trans.shared.b16 {%0,%1,%2,%3}, [%4];"
                 : "=r"(r[0]), "=r"(r[1]), "=r"(r[2]), "=r"(r[3]) : "r"(addr));
}

// ---------------- fused prep: all 4 weight transposes + LN1 in ONE launch --------
#define T_QKV  3072
#define T_PROJ (T_QKV + 1024)
#define T_FC1  (T_PROJ + 4096)
#define T_FC2  (T_FC1 + 4096)
#define PREP_BLOCKS (T_FC2 + MR)

__device__ __forceinline__ void ln_body(const float* __restrict__ x,
                                        const float* __restrict__ g,
                                        const float* __restrict__ beta,
                                        __nv_bfloat16* __restrict__ out,
                                        float* sh, int row, int tid) {
    const float4 v = ((const float4*)(x + (size_t)row * EE))[tid];

    float s = v.x + v.y + v.z + v.w;
    #pragma unroll
    for (int o = 16; o; o >>= 1) s += __shfl_down_sync(0xffffffffu, s, o);
    if ((tid & 31) == 0) sh[tid >> 5] = s;
    __syncthreads();
    if (tid < 32) {
        float t = (tid < 8) ? sh[tid] : 0.f;
        #pragma unroll
        for (int o = 4; o; o >>= 1) t += __shfl_down_sync(0xffffffffu, t, o);
        if (tid == 0) sh[0] = t;
    }
    __syncthreads();
    const float mu = sh[0] * (1.0f / EE);
    __syncthreads();

    float dx = v.x - mu, dy = v.y - mu, dz = v.z - mu, dw = v.w - mu;
    float q = dx * dx + dy * dy + dz * dz + dw * dw;
    #pragma unroll
    for (int o = 16; o; o >>= 1) q += __shfl_down_sync(0xffffffffu, q, o);
    if ((tid & 31) == 0) sh[tid >> 5] = q;
    __syncthreads();
    if (tid < 32) {
        float t = (tid < 8) ? sh[tid] : 0.f;
        #pragma unroll
        for (int o = 4; o; o >>= 1) t += __shfl_down_sync(0xffffffffu, t, o);
        if (tid == 0) sh[0] = t;
    }
    __syncthreads();
    const float rstd = rsqrtf(sh[0] * (1.0f / EE) + 1e-5f);

    const float4 gv = ((const float4*)g)[tid];
    const float4 bv = ((const float4*)beta)[tid];
    uint2 o;
    o.x = pack_bf16(dx * rstd * gv.x + bv.x, dy * rstd * gv.y + bv.y);
    o.y = pack_bf16(dz * rstd * gv.z + bv.z, dw * rstd * gv.w + bv.w);
    ((uint2*)(out + (size_t)row * EE))[tid] = o;
}

__global__ void prep_kernel(const float* __restrict__ w0, const float* __restrict__ w1,
                            const float* __restrict__ w2, const float* __restrict__ w3,
                            __nv_bfloat16* __restrict__ o0, __nv_bfloat16* __restrict__ o1,
                            __nv_bfloat16* __restrict__ o2, __nv_bfloat16* __restrict__ o3,
                            const float* __restrict__ x, const float* __restrict__ g1,
                            const float* __restrict__ beta1, __nv_bfloat16* __restrict__ h) {
    __shared__ float shm[32 * 33];
    const int tid = threadIdx.x;

    if (blockIdx.x >= T_FC2) {
        ln_body(x, g1, beta1, h, shm, blockIdx.x - T_FC2, tid);
        return;
    }

    int tt = blockIdx.x;
    const float* in;
    __nv_bfloat16* out;
    int R, C;
    if (tt < T_QKV)       { in = w0; out = o0; R = EE;   C = 3 * EE; }
    else if (tt < T_PROJ) { in = w1; out = o1; R = EE;   C = EE;   tt -= T_QKV;  }
    else if (tt < T_FC1)  { in = w2; out = o2; R = EE;   C = MLPD; tt -= T_PROJ; }
    else                  { in = w3; out = o3; R = MLPD; C = EE;   tt -= T_FC1;  }
    const int ctiles = C >> 5;
    const int bx = tt % ctiles, by = tt / ctiles;
    const int tx = tid & 31, ty = tid >> 5;

    const int c = bx * 32 + tx;
    const int r0 = by * 32;
    #pragma unroll
    for (int i = ty; i < 32; i += 8)
        shm[i * 33 + tx] = in[(size_t)(r0 + i) * C + c];
    __syncthreads();
    const int rc = by * 32 + tx;
    const int c0 = bx * 32;
    #pragma unroll
    for (int i = ty; i < 32; i += 8)
        out[(size_t)(c0 + i) * R + rc] = __float2bfloat16_rn(shm[tx * 33 + i]);
}

// ---------------- LayerNorm fp32 -> bf16 (standalone, for LN2) -------------------
__global__ void ln_kernel(const float* __restrict__ x, const float* __restrict__ g,
                          const float* __restrict__ beta,
                          __nv_bfloat16* __restrict__ out) {
    __shared__ float sh[8];
    ln_body(x, g, beta, out, sh, blockIdx.x, threadIdx.x);
}

// ---------------- bf16 mma.sync GEMM: CTA 128x128, 128 threads, 4 warps ----------
// Warp tile 64x64 (2m x 2n grid) -> mma:ldsm ratio 4, smem-read pressure halved.
// 3-stage ring, one barrier per K-chunk, occupancy 2.
#define ASTR 72
#define STG  ((128 + 128) * ASTR)
#define GEMM_SMEM_BYTES (3 * STG * 2)   // 110592 bytes -> 2 CTAs/SM

__device__ __forceinline__ void issue_tile(const __nv_bfloat16* __restrict__ A,
                                           const __nv_bfloat16* __restrict__ BT,
                                           __nv_bfloat16* stage, int bm, int bn,
                                           int kc, int K, int tid) {
    __nv_bfloat16* sA = stage;
    __nv_bfloat16* sB = stage + 128 * ASTR;
    #pragma unroll
    for (int p = 0; p < 8; p++) {
        const int e = p * 128 + tid;
        const int row = e >> 3, ch = e & 7;
        cp16(smem_u32(sA + row * ASTR + ch * 8),
             A + (size_t)(bm + row) * K + kc * 64 + ch * 8);
        cp16(smem_u32(sB + row * ASTR + ch * 8),
             BT + (size_t)(bn + row) * K + kc * 64 + ch * 8);
    }
}

template <int EPI>
__global__ __launch_bounds__(128, 2)
void gemm_mma(const __nv_bfloat16* __restrict__ A, const __nv_bfloat16* __restrict__ BT,
              const float* __restrict__ bias, const float* __restrict__ res,
              void* __restrict__ Cout, int M, int N, int K) {
    extern __shared__ __align__(16) __nv_bfloat16 smem[];
    const int tid  = threadIdx.x;
    const int lane = tid & 31, warp = tid >> 5;
    const int wm = warp >> 1, wn = warp & 1;     // 2m x 2n warps, 64x64 warp tiles
    const int gq = lane >> 2, tq = lane & 3;
    const int l15 = lane & 15;
    const int arow = l15, asel = lane >> 4;
    const int g  = lane >> 3, r8 = lane & 7;
    const int brow_off = (g >> 1) * 8 + r8;
    const int bcol_off = (g & 1) * 8;
    const int bm = blockIdx.y << 7;
    const int bn = blockIdx.x << 7;
    const int NC = K >> 6;

    float c[4][8][4];
    #pragma unroll
    for (int i = 0; i < 4; i++)
        #pragma unroll
        for (int j = 0; j < 8; j++)
            #pragma unroll
            for (int k = 0; k < 4; k++) c[i][j][k] = 0.f;

    issue_tile(A, BT, smem,       bm, bn, 0, K, tid); CP_COMMIT();
    issue_tile(A, BT, smem + STG, bm, bn, 1, K, tid); CP_COMMIT();

    int st = 0;
    for (int kc = 0; kc < NC; kc++) {
        CP_WAIT1();
        __syncthreads();
        if (kc + 2 < NC) {
            int nst = st + 2; if (nst >= 3) nst -= 3;
            issue_tile(A, BT, smem + nst * STG, bm, bn, kc + 2, K, tid);
        }
        CP_COMMIT();
        const __nv_bfloat16* sa = smem + st * STG + (size_t)(wm * 64) * ASTR;
        const __nv_bfloat16* sb = smem + st * STG + (size_t)128 * ASTR + (size_t)(wn * 64) * ASTR;
        #pragma unroll
        for (int ks = 0; ks < 4; ks++) {
            uint32_t af[4][4], bf[4][4];
            #pragma unroll
            for (int mt = 0; mt < 4; mt++)
                ldsm_x4(af[mt], smem_u32(sa + (mt * 16 + arow) * ASTR + ks * 16 + asel * 8));
            #pragma unroll
            for (int np = 0; np < 4; np++)
                ldsm_x4(bf[np], smem_u32(sb + (np * 16 + brow_off) * ASTR + ks * 16 + bcol_off));
            #pragma unroll
            for (int mt = 0; mt < 4; mt++)
                #pragma unroll
                for (int np = 0; np < 4; np++) {
                    mma_bf16(c[mt][2 * np + 0], af[mt], bf[np] + 0);
                    mma_bf16(c[mt][2 * np + 1], af[mt], bf[np] + 2);
                }
        }
        if (++st >= 3) st = 0;
    }

    // ---- epilogue ----
    #pragma unroll
    for (int nt = 0; nt < 8; nt++) {
        const int col = bn + wn * 64 + nt * 8 + 2 * tq;
        const float bx = bias[col], by = bias[col + 1];
        #pragma unroll
        for (int mt = 0; mt < 4; mt++) {
            const int row0 = bm + wm * 64 + mt * 16 + gq;
            #pragma unroll
            for (int half = 0; half < 2; half++) {
                const int row = row0 + half * 8;
                float vx = c[mt][nt][half * 2 + 0] + bx;
                float vy = c[mt][nt][half * 2 + 1] + by;
                if (EPI == 1) {
                    vx = 0.5f * vx * (1.0f + erff(vx * 0.70710678118654752f));
                    vy = 0.5f * vy * (1.0f + erff(vy * 0.70710678118654752f));
                }
                if (EPI == 2) {
                    const float2 rv = *(const float2*)(res + (size_t)row * N + col);
                    float2 o; o.x = vx + rv.x; o.y = vy + rv.y;
                    *(float2*)((float*)Cout + (size_t)row * N + col) = o;
                } else {
                    *(uint32_t*)((__nv_bfloat16*)Cout + (size_t)row * N + col) =
                        pack_bf16(vx, vy);
                }
            }
        }
    }
}

// ---------------- Flash attention: 256 queries/CTA, 32 rows/warp (R10) -----------
#define KVS 72
#define NT  (NN / 64)

__global__ __launch_bounds__(256, 1)
void attn_mma(const __nv_bfloat16* __restrict__ qkv, __nv_bfloat16* __restrict__ out) {
    __shared__ __nv_bfloat16 Kb[3][64 * KVS];
    __shared__ __nv_bfloat16 Vb[3][64 * KVS];
    const int tid  = threadIdx.x;
    const int lane = tid & 31, warp = tid >> 5;
    const int gq = lane >> 2, tq = lane & 3;
    const int g  = lane >> 3, r8 = lane & 7;
    const int krow_off = (g >> 1) * 8 + r8;
    const int kcol_off = (g & 1) * 8;
    const int vrow_off = (g & 1) * 8 + r8;
    const int vcol_off = (g >> 1) * 8;
    const int bh = blockIdx.y;
    const int b = bh >> 4, h = bh & 15;
    const int q0 = blockIdx.x * 256;

    uint32_t kbase[3], vbase[3];
    #pragma unroll
    for (int s = 0; s < 3; s++) {
        kbase[s] = smem_u32(&Kb[s][krow_off * KVS + kcol_off]);
        vbase[s] = smem_u32(&Vb[s][vrow_off * KVS + vcol_off]);
    }

    const float qsc = 0.125f * 1.4426950408889634f;
    uint32_t aq[2][4][4];
    #pragma unroll
    for (int mi = 0; mi < 2; mi++) {
        const __nv_bfloat16* r0 =
            qkv + (size_t)(b * NN + q0 + warp * 32 + mi * 16 + gq) * 3072 + h * 64;
        const __nv_bfloat16* r1 = r0 + (size_t)8 * 3072;
        #pragma unroll
        for (int ks = 0; ks < 4; ks++) {
            aq[mi][ks][0] = scale_bf16x2(*(const uint32_t*)(r0 + ks * 16 + 2 * tq), qsc);
            aq[mi][ks][1] = scale_bf16x2(*(const uint32_t*)(r1 + ks * 16 + 2 * tq), qsc);
            aq[mi][ks][2] = scale_bf16x2(*(const uint32_t*)(r0 + ks * 16 + 2 * tq + 8), qsc);
            aq[mi][ks][3] = scale_bf16x2(*(const uint32_t*)(r1 + ks * 16 + 2 * tq + 8), qsc);
        }
    }

    float oc[2][8][4];
    #pragma unroll
    for (int mi = 0; mi < 2; mi++)
        #pragma unroll
        for (int i = 0; i < 8; i++)
            #pragma unroll
            for (int j = 0; j < 4; j++) oc[mi][i][j] = 0.f;
    float mrow[2][2] = { {-1e30f, -1e30f}, {-1e30f, -1e30f} };
    float lrow[2][2] = { {0.f, 0.f}, {0.f, 0.f} };

    auto issue_kv = [&](int buf, int kt) {
        #pragma unroll
        for (int it = 0; it < 2; it++) {
            const int e = it * 256 + tid;
            const int row = e >> 3, ch = e & 7;
            const size_t gbase = (size_t)(b * NN + kt * 64 + row) * 3072 + h * 64 + ch * 8;
            cp16(smem_u32(&Kb[buf][row * KVS + ch * 8]), qkv + gbase + 1024);
            cp16(smem_u32(&Vb[buf][row * KVS + ch * 8]), qkv + gbase + 2048);
        }
    };

    issue_kv(0, 0); CP_COMMIT();
    issue_kv(1, 1); CP_COMMIT();

    int st = 0;
    for (int kt = 0; kt < NT; kt++) {
        CP_WAIT1();
        __syncthreads();
        if (kt + 2 < NT) {
            int nst = st + 2; if (nst >= 3) nst -= 3;
            issue_kv(nst, kt + 2);
        }
        CP_COMMIT();
        const uint32_t ka = kbase[st];
        const uint32_t va = vbase[st];

        float sc[2][8][4];
        #pragma unroll
        for (int mi = 0; mi < 2; mi++)
            #pragma unroll
            for (int i = 0; i < 8; i++)
                #pragma unroll
                for (int j = 0; j < 4; j++) sc[mi][i][j] = 0.f;
        #pragma unroll
        for (int ks = 0; ks < 4; ks++) {
            #pragma unroll
            for (int np = 0; np < 4; np++) {
                uint32_t b4[4];
                ldsm_x4(b4, ka + (uint32_t)((np * 16 * KVS + ks * 16) * 2));
                #pragma unroll
                for (int mi = 0; mi < 2; mi++) {
                    mma_bf16(sc[mi][2 * np + 0], aq[mi][ks], b4 + 0);
                    mma_bf16(sc[mi][2 * np + 1], aq[mi][ks], b4 + 2);
                }
            }
        }

        float f[2][2];
        #pragma unroll
        for (int mi = 0; mi < 2; mi++) {
            float mx0 = -1e30f, mx1 = -1e30f;
            #pragma unroll
            for (int nt = 0; nt < 8; nt++) {
                mx0 = fmaxf(mx0, fmaxf(sc[mi][nt][0], sc[mi][nt][1]));
                mx1 = fmaxf(mx1, fmaxf(sc[mi][nt][2], sc[mi][nt][3]));
            }
            mx0 = fmaxf(mx0, __shfl_xor_sync(0xffffffffu, mx0, 1));
            mx0 = fmaxf(mx0, __shfl_xor_sync(0xffffffffu, mx0, 2));
            mx1 = fmaxf(mx1, __shfl_xor_sync(0xffffffffu, mx1, 1));
            mx1 = fmaxf(mx1, __shfl_xor_sync(0xffffffffu, mx1, 2));
            const float mn0 = fmaxf(mrow[mi][0], mx0);
            const float mn1 = fmaxf(mrow[mi][1], mx1);
            f[mi][0] = ex2(mrow[mi][0] - mn0);
            f[mi][1] = ex2(mrow[mi][1] - mn1);
            mrow[mi][0] = mn0; mrow[mi][1] = mn1;
            lrow[mi][0] *= f[mi][0]; lrow[mi][1] *= f[mi][1];
            #pragma unroll
            for (int dt = 0; dt < 8; dt++) {
                oc[mi][dt][0] *= f[mi][0]; oc[mi][dt][1] *= f[mi][0];
                oc[mi][dt][2] *= f[mi][1]; oc[mi][dt][3] *= f[mi][1];
            }
        }

        #pragma unroll
        for (int j = 0; j < 4; j++) {
            uint32_t pa[2][4];
            #pragma unroll
            for (int mi = 0; mi < 2; mi++) {
                const int t0 = 2 * j, t1 = 2 * j + 1;
                const float m0 = mrow[mi][0], m1 = mrow[mi][1];
                const float p00 = ex2(sc[mi][t0][0] - m0), p01 = ex2(sc[mi][t0][1] - m0);
                const float p02 = ex2(sc[mi][t0][2] - m1), p03 = ex2(sc[mi][t0][3] - m1);
                const float p10 = ex2(sc[mi][t1][0] - m0), p11 = ex2(sc[mi][t1][1] - m0);
                const float p12 = ex2(sc[mi][t1][2] - m1), p13 = ex2(sc[mi][t1][3] - m1);
                lrow[mi][0] += p00 + p01 + p10 + p11;
                lrow[mi][1] += p02 + p03 + p12 + p13;
                pa[mi][0] = pack_bf16(p00, p01); pa[mi][1] = pack_bf16(p02, p03);
                pa[mi][2] = pack_bf16(p10, p11); pa[mi][3] = pack_bf16(p12, p13);
            }
            #pragma unroll
            for (int dp = 0; dp < 4; dp++) {
                uint32_t b4[4];
                ldsm_x4t(b4, va + (uint32_t)((16 * j * KVS + dp * 16) * 2));
                #pragma unroll
                for (int mi = 0; mi < 2; mi++) {
                    mma_bf16(oc[mi][2 * dp + 0], pa[mi], b4 + 0);
                    mma_bf16(oc[mi][2 * dp + 1], pa[mi], b4 + 2);
                }
            }
        }
        if (++st >= 3) st = 0;
    }

    #pragma unroll
    for (int mi = 0; mi < 2; mi++) {
        float l0 = lrow[mi][0], l1 = lrow[mi][1];
        l0 += __shfl_xor_sync(0xffffffffu, l0, 1);
        l0 += __shfl_xor_sync(0xffffffffu, l0, 2);
        l1 += __shfl_xor_sync(0xffffffffu, l1, 1);
        l1 += __shfl_xor_sync(0xffffffffu, l1, 2);
        const float inv0 = 1.f / l0, inv1 = 1.f / l1;
        const int row0 = b * NN + q0 + warp * 32 + mi * 16 + gq;
        __nv_bfloat16* o0 = out + (size_t)row0 * EE + h * 64;
        __nv_bfloat16* o1 = o0 + (size_t)8 * EE;
        #pragma unroll
        for (int dt = 0; dt < 8; dt++) {
            *(uint32_t*)(o0 + dt * 8 + 2 * tq) =
                pack_bf16(oc[mi][dt][0] * inv0, oc[mi][dt][1] * inv0);
            *(uint32_t*)(o1 + dt * 8 + 2 * tq) =
                pack_bf16(oc[mi][dt][2] * inv1, oc[mi][dt][3] * inv1);
        }
    }
}

// ---------------- host launch ---------------------------------------------------
extern "C" void kernel_launch(void* const* d_in, const int* in_sizes, int n_in,
                              void* d_out, int out_size) {
    const float* x      = (const float*)d_in[0];
    const float* w_qkv  = (const float*)d_in[1];
    const float* b_qkv  = (const float*)d_in[2];
    const float* w_proj = (const float*)d_in[3];
    const float* b_proj = (const float*)d_in[4];
    const float* g1     = (const float*)d_in[5];
    const float* beta1  = (const float*)d_in[6];
    const float* g2     = (const float*)d_in[7];
    const float* beta2  = (const float*)d_in[8];
    const float* w_fc1  = (const float*)d_in[9];
    const float* b_fc1  = (const float*)d_in[10];
    const float* w_fc2  = (const float*)d_in[11];
    const float* b_fc2  = (const float*)d_in[12];
    float* out = (float*)d_out;

    __nv_bfloat16 *h, *qkv, *attn, *mlp, *wqkvT, *wprojT, *wfc1T, *wfc2T;
    float* x1;
    cudaGetSymbolAddress((void**)&h,      g_h);
    cudaGetSymbolAddress((void**)&qkv,    g_qkv);
    cudaGetSymbolAddress((void**)&attn,   g_attn);
    cudaGetSymbolAddress((void**)&x1,     g_x1);
    cudaGetSymbolAddress((void**)&mlp,    g_mlp);
    cudaGetSymbolAddress((void**)&wqkvT,  g_wqkvT);
    cudaGetSymbolAddress((void**)&wprojT, g_wprojT);
    cudaGetSymbolAddress((void**)&wfc1T,  g_wfc1T);
    cudaGetSymbolAddress((void**)&wfc2T,  g_wfc2T);

    cudaFuncSetAttribute(gemm_mma<0>, cudaFuncAttributeMaxDynamicSharedMemorySize, GEMM_SMEM_BYTES);
    cudaFuncSetAttribute(gemm_mma<1>, cudaFuncAttributeMaxDynamicSharedMemorySize, GEMM_SMEM_BYTES);
    cudaFuncSetAttribute(gemm_mma<2>, cudaFuncAttributeMaxDynamicSharedMemorySize, GEMM_SMEM_BYTES);

    // 0+1. fused: weight transposes + LN1 in a single launch
    prep_kernel<<<PREP_BLOCKS, 256>>>(w_qkv, w_proj, w_fc1, w_fc2,
                                      wqkvT, wprojT, wfc1T, wfc2T,
                                      x, g1, beta1, h);

    // 2. qkv = h @ w_qkv + b_qkv -> bf16
    gemm_mma<0><<<dim3(3 * EE / 128, MR / 128), 128, GEMM_SMEM_BYTES>>>(
        h, wqkvT, b_qkv, nullptr, qkv, MR, 3 * EE, EE);
    // 3. attention -> bf16 (256 queries per CTA)
    attn_mma<<<dim3(NN / 256, BB * HH), 256>>>(qkv, attn);
    // 4. x1 = attn @ w_proj + b_proj + x -> fp32
    gemm_mma<2><<<dim3(EE / 128, MR / 128), 128, GEMM_SMEM_BYTES>>>(
        attn, wprojT, b_proj, x, x1, MR, EE, EE);
    // 5. h = LN(x1) -> bf16
    ln_kernel<<<MR, 256>>>(x1, g2, beta2, h);
    // 6. mlp = gelu(h @ w_fc1 + b_fc1) -> bf16
    gemm_mma<1><<<dim3(MLPD / 128, MR / 128), 128, GEMM_SMEM_BYTES>>>(
        h, wfc1T, b_fc1, nullptr, mlp, MR, MLPD, EE);
    // 7. out = mlp @ w_fc2 + b_fc2 + x1 -> fp32
    gemm_mma<2><<<dim3(EE / 128, MR / 128), 128, GEMM_SMEM_BYTES>>>(
        mlp, wfc2T, b_fc2, x1, out, MR, EE, MLPD);
}

// round 14
// speedup vs baseline: 1.1298x; 1.0038x over previous
#include <cuda_runtime.h>
#include <cuda_bf16.h>
#include <math.h>
#include <stdint.h>

// Problem constants
#define BB   2
#define NN   2048
#define EE   1024
#define HH   16
#define MLPD 4096
#define MR   (BB * NN)   // 4096 token rows

// ---------------- scratch (static device globals; no allocation) ----------------
__device__ __nv_bfloat16 g_h[MR * EE];               // LN output (bf16)
__device__ __nv_bfloat16 g_qkv[MR * 3 * EE];         // QKV (bf16)
__device__ __nv_bfloat16 g_attn[MR * EE];            // attention out (bf16)
__device__ float         g_x1[MR * EE];              // residual 1 (fp32)
__device__ __nv_bfloat16 g_mlp[(size_t)MR * MLPD];   // GELU(fc1) (bf16)
__device__ __nv_bfloat16 g_wqkvT[3 * EE * EE];       // transposed weights [N,K] bf16
__device__ __nv_bfloat16 g_wprojT[EE * EE];
__device__ __nv_bfloat16 g_wfc1T[(size_t)MLPD * EE];
__device__ __nv_bfloat16 g_wfc2T[(size_t)EE * MLPD];

// ======================= helpers =================================
__device__ __forceinline__ uint32_t smem_u32(const void* p) {
    uint32_t a;
    asm("{ .reg .u64 t; cvta.to.shared.u64 t, %1; cvt.u32.u64 %0, t; }" : "=r"(a) : "l"(p));
    return a;
}
__device__ __forceinline__ float ex2(float x) {
    float r;
    asm("ex2.approx.ftz.f32 %0, %1;" : "=f"(r) : "f"(x));
    return r;
}
__device__ __forceinline__ uint32_t pack_bf16(float lo, float hi) {
    uint32_t r;
    asm("cvt.rn.bf16x2.f32 %0, %1, %2;" : "=r"(r) : "f"(hi), "f"(lo));
    return r;
}
__device__ __forceinline__ uint32_t scale_bf16x2(uint32_t v, float s) {
    const __nv_bfloat162 b = *reinterpret_cast<const __nv_bfloat162*>(&v);
    return pack_bf16(__bfloat162float(b.x) * s, __bfloat162float(b.y) * s);
}
__device__ __forceinline__ void cp16(uint32_t dst, const void* src) {
    asm volatile("cp.async.cg.shared.global [%0], [%1], 16;" :: "r"(dst), "l"(src));
}
#define CP_COMMIT() asm volatile("cp.async.commit_group;" ::: "memory")
#define CP_WAIT1()  asm volatile("cp.async.wait_group 1;" ::: "memory")

__device__ __forceinline__ void mma_bf16(float* c, const uint32_t* a, const uint32_t* b) {
    asm volatile(
        "mma.sync.aligned.m16n8k16.row.col.f32.bf16.bf16.f32 "
        "{%0,%1,%2,%3}, {%4,%5,%6,%7}, {%8,%9}, {%0,%1,%2,%3};"
        : "+f"(c[0]), "+f"(c[1]), "+f"(c[2]), "+f"(c[3])
        : "r"(a[0]), "r"(a[1]), "r"(a[2]), "r"(a[3]), "r"(b[0]), "r"(b[1]));
}
__device__ __forceinline__ void ldsm_x4(uint32_t* r, uint32_t addr) {
    asm volatile("ldmatrix.sync.aligned.m8n8.x4.shared.b16 {%0,%1,%2,%3}, [%4];"
                 : "=r"(r[0]), "=r"(r[1]), "=r"(r[2]), "=r"(r[3]) : "r"(addr));
}
__device__ __forceinline__ void ldsm_x4t(uint32_t* r, uint32_t addr) {
    asm volatile("ldmatrix.sync.aligned.m8n8.x4.trans.shared.b16 {%0,%1,%2,%3}, [%4];"
                 : "=r"(r[0]), "=r"(r[1]), "=r"(r[2]), "=r"(r[3]) : "r"(addr));
}

// ---------------- fused prep: all 4 weight transposes + LN1 in ONE launch --------
#define T_QKV  3072
#define T_PROJ (T_QKV + 1024)
#define T_FC1  (T_PROJ + 4096)
#define T_FC2  (T_FC1 + 4096)
#define PREP_BLOCKS (T_FC2 + MR)

__device__ __forceinline__ void ln_body(const float* __restrict__ x,
                                        const float* __restrict__ g,
                                        const float* __restrict__ beta,
                                        __nv_bfloat16* __restrict__ out,
                                        float* sh, int row, int tid) {
    const float4 v = ((const float4*)(x + (size_t)row * EE))[tid];

    float s = v.x + v.y + v.z + v.w;
    #pragma unroll
    for (int o = 16; o; o >>= 1) s += __shfl_down_sync(0xffffffffu, s, o);
    if ((tid & 31) == 0) sh[tid >> 5] = s;
    __syncthreads();
    if (tid < 32) {
        float t = (tid < 8) ? sh[tid] : 0.f;
        #pragma unroll
        for (int o = 4; o; o >>= 1) t += __shfl_down_sync(0xffffffffu, t, o);
        if (tid == 0) sh[0] = t;
    }
    __syncthreads();
    const float mu = sh[0] * (1.0f / EE);
    __syncthreads();

    float dx = v.x - mu, dy = v.y - mu, dz = v.z - mu, dw = v.w - mu;
    float q = dx * dx + dy * dy + dz * dz + dw * dw;
    #pragma unroll
    for (int o = 16; o; o >>= 1) q += __shfl_down_sync(0xffffffffu, q, o);
    if ((tid & 31) == 0) sh[tid >> 5] = q;
    __syncthreads();
    if (tid < 32) {
        float t = (tid < 8) ? sh[tid] : 0.f;
        #pragma unroll
        for (int o = 4; o; o >>= 1) t += __shfl_down_sync(0xffffffffu, t, o);
        if (tid == 0) sh[0] = t;
    }
    __syncthreads();
    const float rstd = rsqrtf(sh[0] * (1.0f / EE) + 1e-5f);

    const float4 gv = ((const float4*)g)[tid];
    const float4 bv = ((const float4*)beta)[tid];
    uint2 o;
    o.x = pack_bf16(dx * rstd * gv.x + bv.x, dy * rstd * gv.y + bv.y);
    o.y = pack_bf16(dz * rstd * gv.z + bv.z, dw * rstd * gv.w + bv.w);
    ((uint2*)(out + (size_t)row * EE))[tid] = o;
}

__global__ void prep_kernel(const float* __restrict__ w0, const float* __restrict__ w1,
                            const float* __restrict__ w2, const float* __restrict__ w3,
                            __nv_bfloat16* __restrict__ o0, __nv_bfloat16* __restrict__ o1,
                            __nv_bfloat16* __restrict__ o2, __nv_bfloat16* __restrict__ o3,
                            const float* __restrict__ x, const float* __restrict__ g1,
                            const float* __restrict__ beta1, __nv_bfloat16* __restrict__ h) {
    __shared__ float shm[32 * 33];
    const int tid = threadIdx.x;

    if (blockIdx.x >= T_FC2) {
        ln_body(x, g1, beta1, h, shm, blockIdx.x - T_FC2, tid);
        return;
    }

    int tt = blockIdx.x;
    const float* in;
    __nv_bfloat16* out;
    int R, C;
    if (tt < T_QKV)       { in = w0; out = o0; R = EE;   C = 3 * EE; }
    else if (tt < T_PROJ) { in = w1; out = o1; R = EE;   C = EE;   tt -= T_QKV;  }
    else if (tt < T_FC1)  { in = w2; out = o2; R = EE;   C = MLPD; tt -= T_PROJ; }
    else                  { in = w3; out = o3; R = MLPD; C = EE;   tt -= T_FC1;  }
    const int ctiles = C >> 5;
    const int bx = tt % ctiles, by = tt / ctiles;
    const int tx = tid & 31, ty = tid >> 5;

    const int c = bx * 32 + tx;
    const int r0 = by * 32;
    #pragma unroll
    for (int i = ty; i < 32; i += 8)
        shm[i * 33 + tx] = in[(size_t)(r0 + i) * C + c];
    __syncthreads();
    const int rc = by * 32 + tx;
    const int c0 = bx * 32;
    #pragma unroll
    for (int i = ty; i < 32; i += 8)
        out[(size_t)(c0 + i) * R + rc] = __float2bfloat16_rn(shm[tx * 33 + i]);
}

// ---------------- LayerNorm fp32 -> bf16 (standalone, for LN2) -------------------
__global__ void ln_kernel(const float* __restrict__ x, const float* __restrict__ g,
                          const float* __restrict__ beta,
                          __nv_bfloat16* __restrict__ out) {
    __shared__ float sh[8];
    ln_body(x, g, beta, out, sh, blockIdx.x, threadIdx.x);
}

// ---------------- bf16 mma.sync GEMM: CTA 128x128, 128 threads, 4 warps ----------
// (unchanged from R13) Warp tile 64x64; 3-stage ring, 1 barrier/chunk, occ 2.
#define ASTR 72
#define STG  ((128 + 128) * ASTR)
#define GEMM_SMEM_BYTES (3 * STG * 2)   // 110592 bytes -> 2 CTAs/SM

__device__ __forceinline__ void issue_tile(const __nv_bfloat16* __restrict__ A,
                                           const __nv_bfloat16* __restrict__ BT,
                                           __nv_bfloat16* stage, int bm, int bn,
                                           int kc, int K, int tid) {
    __nv_bfloat16* sA = stage;
    __nv_bfloat16* sB = stage + 128 * ASTR;
    #pragma unroll
    for (int p = 0; p < 8; p++) {
        const int e = p * 128 + tid;
        const int row = e >> 3, ch = e & 7;
        cp16(smem_u32(sA + row * ASTR + ch * 8),
             A + (size_t)(bm + row) * K + kc * 64 + ch * 8);
        cp16(smem_u32(sB + row * ASTR + ch * 8),
             BT + (size_t)(bn + row) * K + kc * 64 + ch * 8);
    }
}

template <int EPI>
__global__ __launch_bounds__(128, 2)
void gemm_mma(const __nv_bfloat16* __restrict__ A, const __nv_bfloat16* __restrict__ BT,
              const float* __restrict__ bias, const float* __restrict__ res,
              void* __restrict__ Cout, int M, int N, int K) {
    extern __shared__ __align__(16) __nv_bfloat16 smem[];
    const int tid  = threadIdx.x;
    const int lane = tid & 31, warp = tid >> 5;
    const int wm = warp >> 1, wn = warp & 1;     // 2m x 2n warps, 64x64 warp tiles
    const int gq = lane >> 2, tq = lane & 3;
    const int l15 = lane & 15;
    const int arow = l15, asel = lane >> 4;
    const int g  = lane >> 3, r8 = lane & 7;
    const int brow_off = (g >> 1) * 8 + r8;
    const int bcol_off = (g & 1) * 8;
    const int bm = blockIdx.y << 7;
    const int bn = blockIdx.x << 7;
    const int NC = K >> 6;

    float c[4][8][4];
    #pragma unroll
    for (int i = 0; i < 4; i++)
        #pragma unroll
        for (int j = 0; j < 8; j++)
            #pragma unroll
            for (int k = 0; k < 4; k++) c[i][j][k] = 0.f;

    issue_tile(A, BT, smem,       bm, bn, 0, K, tid); CP_COMMIT();
    issue_tile(A, BT, smem + STG, bm, bn, 1, K, tid); CP_COMMIT();

    int st = 0;
    for (int kc = 0; kc < NC; kc++) {
        CP_WAIT1();
        __syncthreads();
        if (kc + 2 < NC) {
            int nst = st + 2; if (nst >= 3) nst -= 3;
            issue_tile(A, BT, smem + nst * STG, bm, bn, kc + 2, K, tid);
        }
        CP_COMMIT();
        const __nv_bfloat16* sa = smem + st * STG + (size_t)(wm * 64) * ASTR;
        const __nv_bfloat16* sb = smem + st * STG + (size_t)128 * ASTR + (size_t)(wn * 64) * ASTR;
        #pragma unroll
        for (int ks = 0; ks < 4; ks++) {
            uint32_t af[4][4], bf[4][4];
            #pragma unroll
            for (int mt = 0; mt < 4; mt++)
                ldsm_x4(af[mt], smem_u32(sa + (mt * 16 + arow) * ASTR + ks * 16 + asel * 8));
            #pragma unroll
            for (int np = 0; np < 4; np++)
                ldsm_x4(bf[np], smem_u32(sb + (np * 16 + brow_off) * ASTR + ks * 16 + bcol_off));
            #pragma unroll
            for (int mt = 0; mt < 4; mt++)
                #pragma unroll
                for (int np = 0; np < 4; np++) {
                    mma_bf16(c[mt][2 * np + 0], af[mt], bf[np] + 0);
                    mma_bf16(c[mt][2 * np + 1], af[mt], bf[np] + 2);
                }
        }
        if (++st >= 3) st = 0;
    }

    // ---- epilogue ----
    #pragma unroll
    for (int nt = 0; nt < 8; nt++) {
        const int col = bn + wn * 64 + nt * 8 + 2 * tq;
        const float bx = bias[col], by = bias[col + 1];
        #pragma unroll
        for (int mt = 0; mt < 4; mt++) {
            const int row0 = bm + wm * 64 + mt * 16 + gq;
            #pragma unroll
            for (int half = 0; half < 2; half++) {
                const int row = row0 + half * 8;
                float vx = c[mt][nt][half * 2 + 0] + bx;
                float vy = c[mt][nt][half * 2 + 1] + by;
                if (EPI == 1) {
                    vx = 0.5f * vx * (1.0f + erff(vx * 0.70710678118654752f));
                    vy = 0.5f * vy * (1.0f + erff(vy * 0.70710678118654752f));
                }
                if (EPI == 2) {
                    const float2 rv = *(const float2*)(res + (size_t)row * N + col);
                    float2 o; o.x = vx + rv.x; o.y = vy + rv.y;
                    *(float2*)((float*)Cout + (size_t)row * N + col) = o;
                } else {
                    *(uint32_t*)((__nv_bfloat16*)Cout + (size_t)row * N + col) =
                        pack_bf16(vx, vy);
                }
            }
        }
    }
}

// ---------------- Flash attention: 128-key tiles, halved barrier count -----------
// 256 queries/CTA, 32 rows/warp (fragment sharing). 3-stage ring of 128-key
// stages (dynamic smem 216 KB); each barrier covers two 64-key compute halves.
#define KVS 72
#define KSTG (2 * 128 * KVS)               // bf16 elems per stage (K block + V block)
#define ATTN_SMEM_BYTES (3 * KSTG * 2)     // 221184 bytes
#define NT128 (NN / 128)                   // 16 tiles

__global__ __launch_bounds__(256, 1)
void attn_mma(const __nv_bfloat16* __restrict__ qkv, __nv_bfloat16* __restrict__ out) {
    extern __shared__ __align__(16) __nv_bfloat16 asmem[];
    const int tid  = threadIdx.x;
    const int lane = tid & 31, warp = tid >> 5;
    const int gq = lane >> 2, tq = lane & 3;
    const int g  = lane >> 3, r8 = lane & 7;
    const int krow_off = (g >> 1) * 8 + r8;
    const int kcol_off = (g & 1) * 8;
    const int vrow_off = (g & 1) * 8 + r8;
    const int vcol_off = (g >> 1) * 8;
    const int bh = blockIdx.y;
    const int b = bh >> 4, h = bh & 15;
    const int q0 = blockIdx.x * 256;

    const uint32_t sb0 = smem_u32(asmem);
    uint32_t kbase[3], vbase[3];
    #pragma unroll
    for (int s = 0; s < 3; s++) {
        kbase[s] = sb0 + (uint32_t)(s * KSTG * 2) + (uint32_t)((krow_off * KVS + kcol_off) * 2);
        vbase[s] = sb0 + (uint32_t)(s * KSTG * 2 + 128 * KVS * 2)
                       + (uint32_t)((vrow_off * KVS + vcol_off) * 2);
    }

    const float qsc = 0.125f * 1.4426950408889634f;
    uint32_t aq[2][4][4];
    #pragma unroll
    for (int mi = 0; mi < 2; mi++) {
        const __nv_bfloat16* r0 =
            qkv + (size_t)(b * NN + q0 + warp * 32 + mi * 16 + gq) * 3072 + h * 64;
        const __nv_bfloat16* r1 = r0 + (size_t)8 * 3072;
        #pragma unroll
        for (int ks = 0; ks < 4; ks++) {
            aq[mi][ks][0] = scale_bf16x2(*(const uint32_t*)(r0 + ks * 16 + 2 * tq), qsc);
            aq[mi][ks][1] = scale_bf16x2(*(const uint32_t*)(r1 + ks * 16 + 2 * tq), qsc);
            aq[mi][ks][2] = scale_bf16x2(*(const uint32_t*)(r0 + ks * 16 + 2 * tq + 8), qsc);
            aq[mi][ks][3] = scale_bf16x2(*(const uint32_t*)(r1 + ks * 16 + 2 * tq + 8), qsc);
        }
    }

    float oc[2][8][4];
    #pragma unroll
    for (int mi = 0; mi < 2; mi++)
        #pragma unroll
        for (int i = 0; i < 8; i++)
            #pragma unroll
            for (int j = 0; j < 4; j++) oc[mi][i][j] = 0.f;
    float mrow[2][2] = { {-1e30f, -1e30f}, {-1e30f, -1e30f} };
    float lrow[2][2] = { {0.f, 0.f}, {0.f, 0.f} };

    // load one 128-key stage: 128 rows x 8 float4 for K and V each
    auto issue_kv = [&](int buf, int kt) {
        const uint32_t kdst = sb0 + (uint32_t)(buf * KSTG * 2);
        const uint32_t vdst = kdst + (uint32_t)(128 * KVS * 2);
        #pragma unroll
        for (int it = 0; it < 4; it++) {
            const int e = it * 256 + tid;
            const int row = e >> 3, ch = e & 7;
            const size_t gbase = (size_t)(b * NN + kt * 128 + row) * 3072 + h * 64 + ch * 8;
            cp16(kdst + (uint32_t)((row * KVS + ch * 8) * 2), qkv + gbase + 1024);
            cp16(vdst + (uint32_t)((row * KVS + ch * 8) * 2), qkv + gbase + 2048);
        }
    };

    issue_kv(0, 0); CP_COMMIT();
    issue_kv(1, 1); CP_COMMIT();

    int st = 0;  // stage of tile kt
    for (int kt = 0; kt < NT128; kt++) {
        CP_WAIT1();
        __syncthreads();
        if (kt + 2 < NT128) {
            int nst = st + 2; if (nst >= 3) nst -= 3;
            issue_kv(nst, kt + 2);
        }
        CP_COMMIT();

        #pragma unroll
        for (int half = 0; half < 2; half++) {
            const uint32_t ka = kbase[st] + (uint32_t)(half * 64 * KVS * 2);
            const uint32_t va = vbase[st] + (uint32_t)(half * 64 * KVS * 2);

            // ---- S = Q_scaled K^T (log2 domain), both m-tiles per K fragment ----
            float sc[2][8][4];
            #pragma unroll
            for (int mi = 0; mi < 2; mi++)
                #pragma unroll
                for (int i = 0; i < 8; i++)
                    #pragma unroll
                    for (int j = 0; j < 4; j++) sc[mi][i][j] = 0.f;
            #pragma unroll
            for (int ks = 0; ks < 4; ks++) {
                #pragma unroll
                for (int np = 0; np < 4; np++) {
                    uint32_t b4[4];
                    ldsm_x4(b4, ka + (uint32_t)((np * 16 * KVS + ks * 16) * 2));
                    #pragma unroll
                    for (int mi = 0; mi < 2; mi++) {
                        mma_bf16(sc[mi][2 * np + 0], aq[mi][ks], b4 + 0);
                        mma_bf16(sc[mi][2 * np + 1], aq[mi][ks], b4 + 2);
                    }
                }
            }

            // ---- online softmax (exp2 domain), per m-tile ----
            float f[2][2];
            #pragma unroll
            for (int mi = 0; mi < 2; mi++) {
                float mx0 = -1e30f, mx1 = -1e30f;
                #pragma unroll
                for (int nt = 0; nt < 8; nt++) {
                    mx0 = fmaxf(mx0, fmaxf(sc[mi][nt][0], sc[mi][nt][1]));
                    mx1 = fmaxf(mx1, fmaxf(sc[mi][nt][2], sc[mi][nt][3]));
                }
                mx0 = fmaxf(mx0, __shfl_xor_sync(0xffffffffu, mx0, 1));
                mx0 = fmaxf(mx0, __shfl_xor_sync(0xffffffffu, mx0, 2));
                mx1 = fmaxf(mx1, __shfl_xor_sync(0xffffffffu, mx1, 1));
                mx1 = fmaxf(mx1, __shfl_xor_sync(0xffffffffu, mx1, 2));
                const float mn0 = fmaxf(mrow[mi][0], mx0);
                const float mn1 = fmaxf(mrow[mi][1], mx1);
                f[mi][0] = ex2(mrow[mi][0] - mn0);
                f[mi][1] = ex2(mrow[mi][1] - mn1);
                mrow[mi][0] = mn0; mrow[mi][1] = mn1;
                lrow[mi][0] *= f[mi][0]; lrow[mi][1] *= f[mi][1];
                #pragma unroll
                for (int dt = 0; dt < 8; dt++) {
                    oc[mi][dt][0] *= f[mi][0]; oc[mi][dt][1] *= f[mi][0];
                    oc[mi][dt][2] *= f[mi][1]; oc[mi][dt][3] *= f[mi][1];
                }
            }

            // ---- P = exp2(S - m); PV accumulate, both m-tiles per V fragment ----
            #pragma unroll
            for (int j = 0; j < 4; j++) {
                uint32_t pa[2][4];
                #pragma unroll
                for (int mi = 0; mi < 2; mi++) {
                    const int t0 = 2 * j, t1 = 2 * j + 1;
                    const float m0 = mrow[mi][0], m1 = mrow[mi][1];
                    const float p00 = ex2(sc[mi][t0][0] - m0), p01 = ex2(sc[mi][t0][1] - m0);
                    const float p02 = ex2(sc[mi][t0][2] - m1), p03 = ex2(sc[mi][t0][3] - m1);
                    const float p10 = ex2(sc[mi][t1][0] - m0), p11 = ex2(sc[mi][t1][1] - m0);
                    const float p12 = ex2(sc[mi][t1][2] - m1), p13 = ex2(sc[mi][t1][3] - m1);
                    lrow[mi][0] += p00 + p01 + p10 + p11;
                    lrow[mi][1] += p02 + p03 + p12 + p13;
                    pa[mi][0] = pack_bf16(p00, p01); pa[mi][1] = pack_bf16(p02, p03);
                    pa[mi][2] = pack_bf16(p10, p11); pa[mi][3] = pack_bf16(p12, p13);
                }
                #pragma unroll
                for (int dp = 0; dp < 4; dp++) {
                    uint32_t b4[4];
                    ldsm_x4t(b4, va + (uint32_t)((16 * j * KVS + dp * 16) * 2));
                    #pragma unroll
                    for (int mi = 0; mi < 2; mi++) {
                        mma_bf16(oc[mi][2 * dp + 0], pa[mi], b4 + 0);
                        mma_bf16(oc[mi][2 * dp + 1], pa[mi], b4 + 2);
                    }
                }
            }
        }
        if (++st >= 3) st = 0;
    }

    #pragma unroll
    for (int mi = 0; mi < 2; mi++) {
        float l0 = lrow[mi][0], l1 = lrow[mi][1];
        l0 += __shfl_xor_sync(0xffffffffu, l0, 1);
        l0 += __shfl_xor_sync(0xffffffffu, l0, 2);
        l1 += __shfl_xor_sync(0xffffffffu, l1, 1);
        l1 += __shfl_xor_sync(0xffffffffu, l1, 2);
        const float inv0 = 1.f / l0, inv1 = 1.f / l1;
        const int row0 = b * NN + q0 + warp * 32 + mi * 16 + gq;
        __nv_bfloat16* o0 = out + (size_t)row0 * EE + h * 64;
        __nv_bfloat16* o1 = o0 + (size_t)8 * EE;
        #pragma unroll
        for (int dt = 0; dt < 8; dt++) {
            *(uint32_t*)(o0 + dt * 8 + 2 * tq) =
                pack_bf16(oc[mi][dt][0] * inv0, oc[mi][dt][1] * inv0);
            *(uint32_t*)(o1 + dt * 8 + 2 * tq) =
                pack_bf16(oc[mi][dt][2] * inv1, oc[mi][dt][3] * inv1);
        }
    }
}

// ---------------- host launch ---------------------------------------------------
extern "C" void kernel_launch(void* const* d_in, const int* in_sizes, int n_in,
                              void* d_out, int out_size) {
    const float* x      = (const float*)d_in[0];
    const float* w_qkv  = (const float*)d_in[1];
    const float* b_qkv  = (const float*)d_in[2];
    const float* w_proj = (const float*)d_in[3];
    const float* b_proj = (const float*)d_in[4];
    const float* g1     = (const float*)d_in[5];
    const float* beta1  = (const float*)d_in[6];
    const float* g2     = (const float*)d_in[7];
    const float* beta2  = (const float*)d_in[8];
    const float* w_fc1  = (const float*)d_in[9];
    const float* b_fc1  = (const float*)d_in[10];
    const float* w_fc2  = (const float*)d_in[11];
    const float* b_fc2  = (const float*)d_in[12];
    float* out = (float*)d_out;

    __nv_bfloat16 *h, *qkv, *attn, *mlp, *wqkvT, *wprojT, *wfc1T, *wfc2T;
    float* x1;
    cudaGetSymbolAddress((void**)&h,      g_h);
    cudaGetSymbolAddress((void**)&qkv,    g_qkv);
    cudaGetSymbolAddress((void**)&attn,   g_attn);
    cudaGetSymbolAddress((void**)&x1,     g_x1);
    cudaGetSymbolAddress((void**)&mlp,    g_mlp);
    cudaGetSymbolAddress((void**)&wqkvT,  g_wqkvT);
    cudaGetSymbolAddress((void**)&wprojT, g_wprojT);
    cudaGetSymbolAddress((void**)&wfc1T,  g_wfc1T);
    cudaGetSymbolAddress((void**)&wfc2T,  g_wfc2T);

    cudaFuncSetAttribute(gemm_mma<0>, cudaFuncAttributeMaxDynamicSharedMemorySize, GEMM_SMEM_BYTES);
    cudaFuncSetAttribute(gemm_mma<1>, cudaFuncAttributeMaxDynamicSharedMemorySize, GEMM_SMEM_BYTES);
    cudaFuncSetAttribute(gemm_mma<2>, cudaFuncAttributeMaxDynamicSharedMemorySize, GEMM_SMEM_BYTES);
    cudaFuncSetAttribute(attn_mma,    cudaFuncAttributeMaxDynamicSharedMemorySize, ATTN_SMEM_BYTES);

    // 0+1. fused: weight transposes + LN1 in a single launch
    prep_kernel<<<PREP_BLOCKS, 256>>>(w_qkv, w_proj, w_fc1, w_fc2,
                                      wqkvT, wprojT, wfc1T, wfc2T,
                                      x, g1, beta1, h);

    // 2. qkv = h @ w_qkv + b_qkv -> bf16
    gemm_mma<0><<<dim3(3 * EE / 128, MR / 128), 128, GEMM_SMEM_BYTES>>>(
        h, wqkvT, b_qkv, nullptr, qkv, MR, 3 * EE, EE);
    // 3. attention -> bf16 (256 queries per CTA, 128-key tiles)
    attn_mma<<<dim3(NN / 256, BB * HH), 256, ATTN_SMEM_BYTES>>>(qkv, attn);
    // 4. x1 = attn @ w_proj + b_proj + x -> fp32
    gemm_mma<2><<<dim3(EE / 128, MR / 128), 128, GEMM_SMEM_BYTES>>>(
        attn, wprojT, b_proj, x, x1, MR, EE, EE);
    // 5. h = LN(x1) -> bf16
    ln_kernel<<<MR, 256>>>(x1, g2, beta2, h);
    // 6. mlp = gelu(h @ w_fc1 + b_fc1) -> bf16
    gemm_mma<1><<<dim3(MLPD / 128, MR / 128), 128, GEMM_SMEM_BYTES>>>(
        h, wfc1T, b_fc1, nullptr, mlp, MR, MLPD, EE);
    // 7. out = mlp @ w_fc2 + b_fc2 + x1 -> fp32
    gemm_mma<2><<<dim3(EE / 128, MR / 128), 128, GEMM_SMEM_BYTES>>>(
        mlp, wfc2T, b_fc2, x1, out, MR, EE, MLPD);
}